// round 1
// baseline (speedup 1.0000x reference)
#include <cuda_runtime.h>
#include <math.h>

#define MTOK 4096   // B*N
#define DDIM 1024
#define NHEAD 16
#define SEQ 2048
#define TS 16

// ---------------- scratch (device globals; no allocs allowed) ----------------
static __device__ float g_q[MTOK * DDIM];
static __device__ float g_k[MTOK * DDIM];
static __device__ float g_v[MTOK * DDIM];
static __device__ float g_a[MTOK * DDIM];
static __device__ float g_attn[MTOK * DDIM];
static __device__ float g_gate[MTOK * DDIM];
static __device__ float g_normed[MTOK * DDIM];
static __device__ float g_g1[MTOK * 64];
static __device__ float g_lam[MTOK * NHEAD];
static __device__ float g_gam[MTOK * NHEAD];

// ---------------- fp32 SIMT GEMM: C = act(A @ B) ----------------
// A: M x K row-major (row stride K), B: K x Ntot row-major, C: M x Ntot.
// M is blockIdx.y*128 .. +128 (always in range here). N guarded (Ntot may be 64).
// act: 0 none, 1 silu, 2 sigmoid
__global__ __launch_bounds__(256, 2)
void sgemm_k(const float* __restrict__ A, const float* __restrict__ B,
             float* __restrict__ C, int Ntot, int K, int act)
{
    __shared__ __align__(16) float As[16][132];
    __shared__ __align__(16) float Bs[16][128];
    const int m0 = blockIdx.y * 128;
    const int n0 = blockIdx.x * 128;
    const int tid = threadIdx.x;
    const int tx = tid & 15;
    const int ty = tid >> 4;

    float acc[8][8];
#pragma unroll
    for (int i = 0; i < 8; ++i)
#pragma unroll
        for (int j = 0; j < 8; ++j) acc[i][j] = 0.f;

    for (int k0 = 0; k0 < K; k0 += 16) {
#pragma unroll
        for (int i = 0; i < 8; ++i) {
            int id = tid + i * 256;
            int row = id >> 4, kk = id & 15;
            As[kk][row] = A[(m0 + row) * K + (k0 + kk)];
        }
#pragma unroll
        for (int i = 0; i < 8; ++i) {
            int id = tid + i * 256;
            int kk = id >> 7, nn = id & 127;
            int n = n0 + nn;
            Bs[kk][nn] = (n < Ntot) ? B[(k0 + kk) * Ntot + n] : 0.f;
        }
        __syncthreads();
#pragma unroll
        for (int kk = 0; kk < 16; ++kk) {
            float4 a0 = *(const float4*)&As[kk][ty * 8];
            float4 a1 = *(const float4*)&As[kk][ty * 8 + 4];
            float4 b0 = *(const float4*)&Bs[kk][tx * 8];
            float4 b1 = *(const float4*)&Bs[kk][tx * 8 + 4];
            float af[8] = {a0.x, a0.y, a0.z, a0.w, a1.x, a1.y, a1.z, a1.w};
            float bf[8] = {b0.x, b0.y, b0.z, b0.w, b1.x, b1.y, b1.z, b1.w};
#pragma unroll
            for (int i = 0; i < 8; ++i)
#pragma unroll
                for (int j = 0; j < 8; ++j)
                    acc[i][j] = fmaf(af[i], bf[j], acc[i][j]);
        }
        __syncthreads();
    }

#pragma unroll
    for (int i = 0; i < 8; ++i) {
        int row = m0 + ty * 8 + i;
#pragma unroll
        for (int j = 0; j < 8; ++j) {
            int n = n0 + tx * 8 + j;
            if (n < Ntot) {
                float c = acc[i][j];
                if (act == 1)      c = c / (1.f + expf(-c));       // silu
                else if (act == 2) c = 1.f / (1.f + expf(-c));     // sigmoid
                C[row * Ntot + n] = c;
            }
        }
    }
}

// ---------------- per-token f / gamma projections ----------------
// lam = sigmoid(x@Wf) per (token, head)   [= exp(log_sigmoid)]
// gam = -sigmoid(x@Wgamma)
__global__ void k_fgamma(const float* __restrict__ x, const float* __restrict__ Wf,
                         const float* __restrict__ Wg, float* __restrict__ lam,
                         float* __restrict__ gam)
{
    __shared__ float xs[DDIM];
    int t = blockIdx.x;
    int tid = threadIdx.x;  // 128 threads
    for (int i = tid; i < DDIM; i += 128) xs[i] = x[t * DDIM + i];
    __syncthreads();
    int idx = tid >> 2;     // 0..31 (0..15: f, 16..31: gamma)
    int part = tid & 3;
    int col = idx & 15;
    const float* W = (idx < 16) ? Wf : Wg;
    float s = 0.f;
    int i0 = part * 256;
#pragma unroll 8
    for (int i = 0; i < 256; ++i)
        s = fmaf(xs[i0 + i], W[(i0 + i) * NHEAD + col], s);
    s += __shfl_xor_sync(0xffffffffu, s, 1);
    s += __shfl_xor_sync(0xffffffffu, s, 2);
    if (part == 0) {
        float sg = 1.f / (1.f + expf(-s));
        if (idx < 16) lam[t * NHEAD + col] = sg;
        else          gam[t * NHEAD + col] = -sg;
    }
}

// ---------------- l2norm(k) per head; a = k_norm * gamma * lambda ----------------
__global__ void k_norm_a(float* __restrict__ k, const float* __restrict__ lam,
                         const float* __restrict__ gam, float* __restrict__ a)
{
    int t = blockIdx.x;
    int w = threadIdx.x >> 5;    // head (512 threads = 16 warps)
    int lane = threadIdx.x & 31;
    int base = t * DDIM + w * 64;
    float k0 = k[base + lane], k1 = k[base + lane + 32];
    float ss = k0 * k0 + k1 * k1;
#pragma unroll
    for (int o = 16; o; o >>= 1) ss += __shfl_xor_sync(0xffffffffu, ss, o);
    float inv = 1.f / fmaxf(sqrtf(ss), 1e-12f);
    float c = gam[t * NHEAD + w] * lam[t * NHEAD + w];
    float kn0 = k0 * inv, kn1 = k1 * inv;
    k[base + lane] = kn0;       k[base + lane + 32] = kn1;
    a[base + lane] = kn0 * c;   a[base + lane + 32] = kn1 * c;
}

// ---------------- delta-rule scan ----------------
// Column-independent recurrence: for each value-column v,
//   sp = lam_t * s;  u = dot(a_t, sp) + v_t[v];  s = sp + k_t * u;  o_t[v] = dot(q_t, s)
// grid: 128 blocks = (b,h) x 4 column-quarters; block: 128 thr = 16 cols x 8 subs,
// each thread holds 8 state rows in registers.
__global__ void k_scan(const float* __restrict__ q, const float* __restrict__ k,
                       const float* __restrict__ v, const float* __restrict__ a,
                       const float* __restrict__ lamArr, float* __restrict__ o)
{
    __shared__ __align__(16) float qs[TS][64];
    __shared__ __align__(16) float ks[TS][64];
    __shared__ __align__(16) float as_[TS][64];
    __shared__ float vs[TS][16];
    __shared__ float lm[TS];

    int blk = blockIdx.x;           // 0..127
    int bh = blk >> 2;
    int quarter = blk & 3;
    int b = bh >> 4, h = bh & 15;
    int tid = threadIdx.x;          // 0..127
    int col_local = tid >> 3;       // 0..15
    int sub = tid & 7;
    int tok0 = b * SEQ;
    int hoff = h * 64;

    float s0 = 0, s1 = 0, s2 = 0, s3 = 0, s4 = 0, s5 = 0, s6 = 0, s7 = 0;

    for (int st = 0; st < SEQ / TS; ++st) {
        __syncthreads();
        int tb = tok0 + st * TS;
#pragma unroll
        for (int i = 0; i < 8; ++i) { int id = tid + i * 128; int tt = id >> 6, cc = id & 63;
            qs[tt][cc] = q[(tb + tt) * DDIM + hoff + cc]; }
#pragma unroll
        for (int i = 0; i < 8; ++i) { int id = tid + i * 128; int tt = id >> 6, cc = id & 63;
            ks[tt][cc] = k[(tb + tt) * DDIM + hoff + cc]; }
#pragma unroll
        for (int i = 0; i < 8; ++i) { int id = tid + i * 128; int tt = id >> 6, cc = id & 63;
            as_[tt][cc] = a[(tb + tt) * DDIM + hoff + cc]; }
#pragma unroll
        for (int i = 0; i < 2; ++i) { int id = tid + i * 128; int tt = id >> 4, cl = id & 15;
            vs[tt][cl] = v[(tb + tt) * DDIM + hoff + quarter * 16 + cl]; }
        if (tid < TS) lm[tid] = lamArr[(tb + tid) * NHEAD + h];
        __syncthreads();

#pragma unroll 4
        for (int tt = 0; tt < TS; ++tt) {
            float l = lm[tt];
            float4 a0 = *(const float4*)&as_[tt][sub * 8];
            float4 a1 = *(const float4*)&as_[tt][sub * 8 + 4];
            float sp0 = s0 * l, sp1 = s1 * l, sp2 = s2 * l, sp3 = s3 * l;
            float sp4 = s4 * l, sp5 = s5 * l, sp6 = s6 * l, sp7 = s7 * l;
            float up = a0.x * sp0 + a0.y * sp1 + a0.z * sp2 + a0.w * sp3
                     + a1.x * sp4 + a1.y * sp5 + a1.z * sp6 + a1.w * sp7;
            up += __shfl_xor_sync(0xffffffffu, up, 1);
            up += __shfl_xor_sync(0xffffffffu, up, 2);
            up += __shfl_xor_sync(0xffffffffu, up, 4);
            float u = up + vs[tt][col_local];
            float4 kv0 = *(const float4*)&ks[tt][sub * 8];
            float4 kv1 = *(const float4*)&ks[tt][sub * 8 + 4];
            s0 = fmaf(kv0.x, u, sp0); s1 = fmaf(kv0.y, u, sp1);
            s2 = fmaf(kv0.z, u, sp2); s3 = fmaf(kv0.w, u, sp3);
            s4 = fmaf(kv1.x, u, sp4); s5 = fmaf(kv1.y, u, sp5);
            s6 = fmaf(kv1.z, u, sp6); s7 = fmaf(kv1.w, u, sp7);
            float4 qv0 = *(const float4*)&qs[tt][sub * 8];
            float4 qv1 = *(const float4*)&qs[tt][sub * 8 + 4];
            float op = qv0.x * s0 + qv0.y * s1 + qv0.z * s2 + qv0.w * s3
                     + qv1.x * s4 + qv1.y * s5 + qv1.z * s6 + qv1.w * s7;
            op += __shfl_xor_sync(0xffffffffu, op, 1);
            op += __shfl_xor_sync(0xffffffffu, op, 2);
            op += __shfl_xor_sync(0xffffffffu, op, 4);
            if (sub == 0)
                o[(tb + tt) * DDIM + hoff + quarter * 16 + col_local] = op;
        }
    }
}

// ---------------- gate-multiply + LayerNorm (weight only) ----------------
__global__ void k_ln(const float* __restrict__ attn, const float* __restrict__ gate,
                     const float* __restrict__ nw, float* __restrict__ out)
{
    __shared__ float red[32];
    int t = blockIdx.x;
    int tid = threadIdx.x;  // 256
    int lane = tid & 31, w = tid >> 5;
    float y[4];
    float s = 0.f;
#pragma unroll
    for (int i = 0; i < 4; ++i) {
        int j = tid + i * 256;
        y[i] = attn[t * DDIM + j] * gate[t * DDIM + j];
        s += y[i];
    }
#pragma unroll
    for (int o = 16; o; o >>= 1) s += __shfl_xor_sync(0xffffffffu, s, o);
    if (lane == 0) red[w] = s;
    __syncthreads();
    if (w == 0) {
        float v2 = (lane < 8) ? red[lane] : 0.f;
#pragma unroll
        for (int o = 4; o; o >>= 1) v2 += __shfl_xor_sync(0xffffffffu, v2, o);
        if (lane == 0) red[0] = v2;
    }
    __syncthreads();
    float mu = red[0] * (1.f / DDIM);
    __syncthreads();
    float vsum = 0.f;
#pragma unroll
    for (int i = 0; i < 4; ++i) { float d = y[i] - mu; vsum += d * d; }
#pragma unroll
    for (int o = 16; o; o >>= 1) vsum += __shfl_xor_sync(0xffffffffu, vsum, o);
    if (lane == 0) red[w] = vsum;
    __syncthreads();
    if (w == 0) {
        float v2 = (lane < 8) ? red[lane] : 0.f;
#pragma unroll
        for (int o = 4; o; o >>= 1) v2 += __shfl_xor_sync(0xffffffffu, v2, o);
        if (lane == 0) red[0] = v2;
    }
    __syncthreads();
    float inv = rsqrtf(red[0] * (1.f / DDIM) + 1e-5f);
#pragma unroll
    for (int i = 0; i < 4; ++i) {
        int j = tid + i * 256;
        out[t * DDIM + j] = (y[i] - mu) * inv * nw[j];
    }
}

// ---------------- launch ----------------
extern "C" void kernel_launch(void* const* d_in, const int* in_sizes, int n_in,
                              void* d_out, int out_size)
{
    const float* x      = (const float*)d_in[0];
    const float* Wq     = (const float*)d_in[1];
    const float* Wk     = (const float*)d_in[2];
    const float* Wv     = (const float*)d_in[3];
    const float* Wgamma = (const float*)d_in[4];
    const float* Wf     = (const float*)d_in[5];
    const float* Wg1    = (const float*)d_in[6];
    const float* Wg2    = (const float*)d_in[7];
    const float* Wo     = (const float*)d_in[8];
    const float* nw     = (const float*)d_in[9];
    float* out = (float*)d_out;

    float *q, *k, *v, *a, *attn, *gate, *normed, *g1, *lam, *gam;
    cudaGetSymbolAddress((void**)&q, g_q);
    cudaGetSymbolAddress((void**)&k, g_k);
    cudaGetSymbolAddress((void**)&v, g_v);
    cudaGetSymbolAddress((void**)&a, g_a);
    cudaGetSymbolAddress((void**)&attn, g_attn);
    cudaGetSymbolAddress((void**)&gate, g_gate);
    cudaGetSymbolAddress((void**)&normed, g_normed);
    cudaGetSymbolAddress((void**)&g1, g_g1);
    cudaGetSymbolAddress((void**)&lam, g_lam);
    cudaGetSymbolAddress((void**)&gam, g_gam);

    dim3 gFull(DDIM / 128, MTOK / 128);   // (8, 32)
    dim3 gG1(1, MTOK / 128);              // N = 64

    sgemm_k<<<gFull, 256>>>(x, Wq, q, DDIM, DDIM, 1);      // q = silu(x@Wq)
    sgemm_k<<<gFull, 256>>>(x, Wk, k, DDIM, DDIM, 1);      // k = silu(x@Wk)
    sgemm_k<<<gFull, 256>>>(x, Wv, v, DDIM, DDIM, 1);      // v = silu(x@Wv)
    k_fgamma<<<MTOK, 128>>>(x, Wf, Wgamma, lam, gam);      // lam, gamma
    k_norm_a<<<MTOK, 512>>>(k, lam, gam, a);               // k := l2norm(k); a = k*gamma*lam
    k_scan<<<128, 128>>>(q, k, v, a, lam, attn);           // delta-rule recurrence
    sgemm_k<<<gG1, 256>>>(x, Wg1, g1, 64, DDIM, 0);        // g1 = x@Wg1
    sgemm_k<<<gFull, 256>>>(g1, Wg2, gate, DDIM, 64, 2);   // gate = sigmoid(g1@Wg2)
    k_ln<<<MTOK, 256>>>(attn, gate, nw, normed);           // gated + LayerNorm
    sgemm_k<<<gFull, 256>>>(normed, Wo, out, DDIM, DDIM, 0); // out = normed@Wo
}

// round 2
// speedup vs baseline: 1.0898x; 1.0898x over previous
#include <cuda_runtime.h>
#include <math.h>

#define MTOK 4096   // B*N
#define DDIM 1024
#define NHEAD 16
#define SEQ 2048
#define TS 16

// ---------------- scratch (device globals; no allocs allowed) ----------------
static __device__ float g_q[MTOK * DDIM];
static __device__ float g_k[MTOK * DDIM];
static __device__ float g_v[MTOK * DDIM];
static __device__ float g_a[MTOK * DDIM];
static __device__ float g_attn[MTOK * DDIM];
static __device__ float g_gate[MTOK * DDIM];
static __device__ float g_normed[MTOK * DDIM];
static __device__ float g_g1[MTOK * 64];
static __device__ float g_lam[MTOK * NHEAD];
static __device__ float g_gam[MTOK * NHEAD];

__device__ __forceinline__ float to_tf32(float f) {
    asm("cvt.rna.tf32.f32 %0, %0;" : "+f"(f));
    return f;
}

// ---------------- tf32 tensor-core GEMM: C = act(A @ B) ----------------
// A: M x K row-major, B: K x Ntot row-major, C: M x Ntot row-major.
// Block tile 128x128, K-tile 32. 256 threads = 8 warps, warp tile 64x32.
// mma.sync.m16n8k8.tf32. Fragment-major smem layout -> conflict-free LDS.128/64.
// act: 0 none, 1 silu, 2 sigmoid. M must be mult of 128, K mult of 32.
__global__ __launch_bounds__(256)
void tgemm_k(const float* __restrict__ A, const float* __restrict__ B,
             float* __restrict__ C, int Ntot, int K, int act)
{
    __shared__ __align__(16) float As[4096];   // [s(4)][mt(8)][lane(32)][j(4)]
    __shared__ __align__(16) float Bs[4096];   // [s(4)][nt(16)][lane(32)][j(2)]

    const int tid  = threadIdx.x;
    const int lane = tid & 31;
    const int warp = tid >> 5;
    const int wm   = warp >> 2;     // 0..1 -> m offset wm*64
    const int wn   = warp & 3;      // 0..3 -> n offset wn*32
    const int g    = lane >> 2;     // groupID 0..7
    const int tig  = lane & 3;      // thread-in-group 0..3
    const int m0   = blockIdx.y * 128;
    const int n0   = blockIdx.x * 128;

    float acc[4][4][4];
#pragma unroll
    for (int mt = 0; mt < 4; ++mt)
#pragma unroll
        for (int nt = 0; nt < 4; ++nt)
#pragma unroll
            for (int j = 0; j < 4; ++j) acc[mt][nt][j] = 0.f;

    float4 stA[4], stB[4];

    const int KT = K / 32;

    // ---- stage tile kt=0 ----
    {
        int k0 = 0;
#pragma unroll
        for (int i = 0; i < 4; ++i) {
            int idx = tid + i * 256;
            int row = idx >> 3, c4 = idx & 7;
            stA[i] = *(const float4*)&A[(size_t)(m0 + row) * K + k0 + c4 * 4];
            int krow = idx >> 5, c4b = idx & 31;
            int n = n0 + c4b * 4;
            if (n < Ntot) stB[i] = *(const float4*)&B[(size_t)(k0 + krow) * Ntot + n];
            else          stB[i] = make_float4(0.f, 0.f, 0.f, 0.f);
        }
    }

    for (int kt = 0; kt < KT; ++kt) {
        // ---- store staged regs to smem (fragment-major, tf32-rounded) ----
#pragma unroll
        for (int i = 0; i < 4; ++i) {
            int idx = tid + i * 256;
            // A element (row, col=c4*4+e)
            int row = idx >> 3, c4 = idx & 7;
            int s = c4 >> 1, jb1 = c4 & 1;
            int mt = row >> 4, gg = row & 7, jb0 = (row >> 3) & 1;
            int j = jb0 + 2 * jb1;
            int abase = (s * 8 + mt) * 128 + gg * 16 + j;
            float av[4] = {stA[i].x, stA[i].y, stA[i].z, stA[i].w};
#pragma unroll
            for (int e = 0; e < 4; ++e) As[abase + e * 4] = to_tf32(av[e]);
            // B element (krow, n=c4b*4+e)
            int krow = idx >> 5, c4b = idx & 31;
            int sb = krow >> 3, cc = krow & 7;
            int jB = cc >> 2, cB = cc & 3;
            int nt = c4b >> 1, gb0 = (c4b & 1) * 4;
            int bbase = (sb * 16 + nt) * 64 + cB * 2 + jB;
            float bv[4] = {stB[i].x, stB[i].y, stB[i].z, stB[i].w};
#pragma unroll
            for (int e = 0; e < 4; ++e) Bs[bbase + (gb0 + e) * 8] = to_tf32(bv[e]);
        }
        __syncthreads();

        // ---- prefetch next tile to regs ----
        if (kt + 1 < KT) {
            int k0 = (kt + 1) * 32;
#pragma unroll
            for (int i = 0; i < 4; ++i) {
                int idx = tid + i * 256;
                int row = idx >> 3, c4 = idx & 7;
                stA[i] = *(const float4*)&A[(size_t)(m0 + row) * K + k0 + c4 * 4];
                int krow = idx >> 5, c4b = idx & 31;
                int n = n0 + c4b * 4;
                if (n < Ntot) stB[i] = *(const float4*)&B[(size_t)(k0 + krow) * Ntot + n];
                else          stB[i] = make_float4(0.f, 0.f, 0.f, 0.f);
            }
        }

        // ---- compute: 4 k-steps x (4 mtiles x 4 ntiles) mma ----
#pragma unroll
        for (int s = 0; s < 4; ++s) {
            float4 af[4];
            float2 bf[4];
#pragma unroll
            for (int mt = 0; mt < 4; ++mt)
                af[mt] = *(const float4*)&As[(s * 8 + wm * 4 + mt) * 128 + lane * 4];
#pragma unroll
            for (int nt = 0; nt < 4; ++nt)
                bf[nt] = *(const float2*)&Bs[(s * 16 + wn * 4 + nt) * 64 + lane * 2];
#pragma unroll
            for (int mt = 0; mt < 4; ++mt)
#pragma unroll
                for (int nt = 0; nt < 4; ++nt) {
                    asm volatile(
                        "mma.sync.aligned.m16n8k8.row.col.f32.tf32.tf32.f32 "
                        "{%0,%1,%2,%3}, {%4,%5,%6,%7}, {%8,%9}, {%0,%1,%2,%3};"
                        : "+f"(acc[mt][nt][0]), "+f"(acc[mt][nt][1]),
                          "+f"(acc[mt][nt][2]), "+f"(acc[mt][nt][3])
                        : "r"(__float_as_uint(af[mt].x)), "r"(__float_as_uint(af[mt].y)),
                          "r"(__float_as_uint(af[mt].z)), "r"(__float_as_uint(af[mt].w)),
                          "r"(__float_as_uint(bf[nt].x)), "r"(__float_as_uint(bf[nt].y)));
                }
        }
        __syncthreads();
    }

    // ---- epilogue ----
#pragma unroll
    for (int mt = 0; mt < 4; ++mt) {
        int row = m0 + wm * 64 + mt * 16 + g;
#pragma unroll
        for (int nt = 0; nt < 4; ++nt) {
            int col = n0 + wn * 32 + nt * 8 + tig * 2;
            if (col < Ntot) {
                float c0 = acc[mt][nt][0], c1 = acc[mt][nt][1];
                float c2 = acc[mt][nt][2], c3 = acc[mt][nt][3];
                if (act == 1) {
                    c0 = c0 / (1.f + expf(-c0)); c1 = c1 / (1.f + expf(-c1));
                    c2 = c2 / (1.f + expf(-c2)); c3 = c3 / (1.f + expf(-c3));
                } else if (act == 2) {
                    c0 = 1.f / (1.f + expf(-c0)); c1 = 1.f / (1.f + expf(-c1));
                    c2 = 1.f / (1.f + expf(-c2)); c3 = 1.f / (1.f + expf(-c3));
                }
                *(float2*)&C[(size_t)row * Ntot + col]       = make_float2(c0, c1);
                *(float2*)&C[(size_t)(row + 8) * Ntot + col] = make_float2(c2, c3);
            }
        }
    }
}

// ---------------- per-token f / gamma projections (tiled skinny GEMM) ----------------
// lam = sigmoid(x@Wf), gam = -sigmoid(x@Wgamma); 32 output cols (16 f | 16 gamma).
__global__ void k_fgamma(const float* __restrict__ x, const float* __restrict__ Wf,
                         const float* __restrict__ Wg, float* __restrict__ lam,
                         float* __restrict__ gam)
{
    __shared__ float xs[32][33];
    __shared__ float Ws[32][32];
    int t0 = blockIdx.x * 32;
    int tid = threadIdx.x;      // 256
    int c = tid & 31, tg = tid >> 5;   // tg 0..7 -> 4 tokens each
    float acc[4] = {0.f, 0.f, 0.f, 0.f};

    for (int k0 = 0; k0 < DDIM; k0 += 32) {
        __syncthreads();
#pragma unroll
        for (int i = 0; i < 4; ++i) {
            int idx = tid + i * 256;
            int tt = idx >> 5, kk = idx & 31;
            xs[tt][kk] = x[(t0 + tt) * DDIM + k0 + kk];
            int kr = idx >> 5, col = idx & 31;
            Ws[kr][col] = (col < 16) ? Wf[(k0 + kr) * NHEAD + col]
                                     : Wg[(k0 + kr) * NHEAD + (col - 16)];
        }
        __syncthreads();
#pragma unroll 8
        for (int kk = 0; kk < 32; ++kk) {
            float w = Ws[kk][c];
#pragma unroll
            for (int i = 0; i < 4; ++i)
                acc[i] = fmaf(xs[tg * 4 + i][kk], w, acc[i]);
        }
    }
#pragma unroll
    for (int i = 0; i < 4; ++i) {
        int t = t0 + tg * 4 + i;
        float sg = 1.f / (1.f + expf(-acc[i]));
        if (c < 16) lam[t * NHEAD + c] = sg;
        else        gam[t * NHEAD + (c - 16)] = -sg;
    }
}

// ---------------- l2norm(k) per head; a = k_norm * gamma * lambda ----------------
__global__ void k_norm_a(float* __restrict__ k, const float* __restrict__ lam,
                         const float* __restrict__ gam, float* __restrict__ a)
{
    int t = blockIdx.x;
    int w = threadIdx.x >> 5;    // head (512 threads = 16 warps)
    int lane = threadIdx.x & 31;
    int base = t * DDIM + w * 64;
    float k0 = k[base + lane], k1 = k[base + lane + 32];
    float ss = k0 * k0 + k1 * k1;
#pragma unroll
    for (int o = 16; o; o >>= 1) ss += __shfl_xor_sync(0xffffffffu, ss, o);
    float inv = 1.f / fmaxf(sqrtf(ss), 1e-12f);
    float c = gam[t * NHEAD + w] * lam[t * NHEAD + w];
    float kn0 = k0 * inv, kn1 = k1 * inv;
    k[base + lane] = kn0;       k[base + lane + 32] = kn1;
    a[base + lane] = kn0 * c;   a[base + lane + 32] = kn1 * c;
}

// ---------------- delta-rule scan ----------------
__global__ void k_scan(const float* __restrict__ q, const float* __restrict__ k,
                       const float* __restrict__ v, const float* __restrict__ a,
                       const float* __restrict__ lamArr, float* __restrict__ o)
{
    __shared__ __align__(16) float qs[TS][64];
    __shared__ __align__(16) float ks[TS][64];
    __shared__ __align__(16) float as_[TS][64];
    __shared__ float vs[TS][16];
    __shared__ float lm[TS];

    int blk = blockIdx.x;           // 0..127
    int bh = blk >> 2;
    int quarter = blk & 3;
    int b = bh >> 4, h = bh & 15;
    int tid = threadIdx.x;          // 0..127
    int col_local = tid >> 3;       // 0..15
    int sub = tid & 7;
    int tok0 = b * SEQ;
    int hoff = h * 64;

    float s0 = 0, s1 = 0, s2 = 0, s3 = 0, s4 = 0, s5 = 0, s6 = 0, s7 = 0;

    for (int st = 0; st < SEQ / TS; ++st) {
        __syncthreads();
        int tb = tok0 + st * TS;
#pragma unroll
        for (int i = 0; i < 8; ++i) { int id = tid + i * 128; int tt = id >> 6, cc = id & 63;
            qs[tt][cc] = q[(tb + tt) * DDIM + hoff + cc]; }
#pragma unroll
        for (int i = 0; i < 8; ++i) { int id = tid + i * 128; int tt = id >> 6, cc = id & 63;
            ks[tt][cc] = k[(tb + tt) * DDIM + hoff + cc]; }
#pragma unroll
        for (int i = 0; i < 8; ++i) { int id = tid + i * 128; int tt = id >> 6, cc = id & 63;
            as_[tt][cc] = a[(tb + tt) * DDIM + hoff + cc]; }
#pragma unroll
        for (int i = 0; i < 2; ++i) { int id = tid + i * 128; int tt = id >> 4, cl = id & 15;
            vs[tt][cl] = v[(tb + tt) * DDIM + hoff + quarter * 16 + cl]; }
        if (tid < TS) lm[tid] = lamArr[(tb + tid) * NHEAD + h];
        __syncthreads();

#pragma unroll 4
        for (int tt = 0; tt < TS; ++tt) {
            float l = lm[tt];
            float4 a0 = *(const float4*)&as_[tt][sub * 8];
            float4 a1 = *(const float4*)&as_[tt][sub * 8 + 4];
            float sp0 = s0 * l, sp1 = s1 * l, sp2 = s2 * l, sp3 = s3 * l;
            float sp4 = s4 * l, sp5 = s5 * l, sp6 = s6 * l, sp7 = s7 * l;
            float up = a0.x * sp0 + a0.y * sp1 + a0.z * sp2 + a0.w * sp3
                     + a1.x * sp4 + a1.y * sp5 + a1.z * sp6 + a1.w * sp7;
            up += __shfl_xor_sync(0xffffffffu, up, 1);
            up += __shfl_xor_sync(0xffffffffu, up, 2);
            up += __shfl_xor_sync(0xffffffffu, up, 4);
            float u = up + vs[tt][col_local];
            float4 kv0 = *(const float4*)&ks[tt][sub * 8];
            float4 kv1 = *(const float4*)&ks[tt][sub * 8 + 4];
            s0 = fmaf(kv0.x, u, sp0); s1 = fmaf(kv0.y, u, sp1);
            s2 = fmaf(kv0.z, u, sp2); s3 = fmaf(kv0.w, u, sp3);
            s4 = fmaf(kv1.x, u, sp4); s5 = fmaf(kv1.y, u, sp5);
            s6 = fmaf(kv1.z, u, sp6); s7 = fmaf(kv1.w, u, sp7);
            float4 qv0 = *(const float4*)&qs[tt][sub * 8];
            float4 qv1 = *(const float4*)&qs[tt][sub * 8 + 4];
            float op = qv0.x * s0 + qv0.y * s1 + qv0.z * s2 + qv0.w * s3
                     + qv1.x * s4 + qv1.y * s5 + qv1.z * s6 + qv1.w * s7;
            op += __shfl_xor_sync(0xffffffffu, op, 1);
            op += __shfl_xor_sync(0xffffffffu, op, 2);
            op += __shfl_xor_sync(0xffffffffu, op, 4);
            if (sub == 0)
                o[(tb + tt) * DDIM + hoff + quarter * 16 + col_local] = op;
        }
    }
}

// ---------------- gate-multiply + LayerNorm (weight only) ----------------
__global__ void k_ln(const float* __restrict__ attn, const float* __restrict__ gate,
                     const float* __restrict__ nw, float* __restrict__ out)
{
    __shared__ float red[32];
    int t = blockIdx.x;
    int tid = threadIdx.x;  // 256
    int lane = tid & 31, w = tid >> 5;
    float y[4];
    float s = 0.f;
#pragma unroll
    for (int i = 0; i < 4; ++i) {
        int j = tid + i * 256;
        y[i] = attn[t * DDIM + j] * gate[t * DDIM + j];
        s += y[i];
    }
#pragma unroll
    for (int o = 16; o; o >>= 1) s += __shfl_xor_sync(0xffffffffu, s, o);
    if (lane == 0) red[w] = s;
    __syncthreads();
    if (w == 0) {
        float v2 = (lane < 8) ? red[lane] : 0.f;
#pragma unroll
        for (int o = 4; o; o >>= 1) v2 += __shfl_xor_sync(0xffffffffu, v2, o);
        if (lane == 0) red[0] = v2;
    }
    __syncthreads();
    float mu = red[0] * (1.f / DDIM);
    __syncthreads();
    float vsum = 0.f;
#pragma unroll
    for (int i = 0; i < 4; ++i) { float d = y[i] - mu; vsum += d * d; }
#pragma unroll
    for (int o = 16; o; o >>= 1) vsum += __shfl_xor_sync(0xffffffffu, vsum, o);
    if (lane == 0) red[w] = vsum;
    __syncthreads();
    if (w == 0) {
        float v2 = (lane < 8) ? red[lane] : 0.f;
#pragma unroll
        for (int o = 4; o; o >>= 1) v2 += __shfl_xor_sync(0xffffffffu, v2, o);
        if (lane == 0) red[0] = v2;
    }
    __syncthreads();
    float inv = rsqrtf(red[0] * (1.f / DDIM) + 1e-5f);
#pragma unroll
    for (int i = 0; i < 4; ++i) {
        int j = tid + i * 256;
        out[t * DDIM + j] = (y[i] - mu) * inv * nw[j];
    }
}

// ---------------- launch ----------------
extern "C" void kernel_launch(void* const* d_in, const int* in_sizes, int n_in,
                              void* d_out, int out_size)
{
    const float* x      = (const float*)d_in[0];
    const float* Wq     = (const float*)d_in[1];
    const float* Wk     = (const float*)d_in[2];
    const float* Wv     = (const float*)d_in[3];
    const float* Wgamma = (const float*)d_in[4];
    const float* Wf     = (const float*)d_in[5];
    const float* Wg1    = (const float*)d_in[6];
    const float* Wg2    = (const float*)d_in[7];
    const float* Wo     = (const float*)d_in[8];
    const float* nw     = (const float*)d_in[9];
    float* out = (float*)d_out;

    float *q, *k, *v, *a, *attn, *gate, *normed, *g1, *lam, *gam;
    cudaGetSymbolAddress((void**)&q, g_q);
    cudaGetSymbolAddress((void**)&k, g_k);
    cudaGetSymbolAddress((void**)&v, g_v);
    cudaGetSymbolAddress((void**)&a, g_a);
    cudaGetSymbolAddress((void**)&attn, g_attn);
    cudaGetSymbolAddress((void**)&gate, g_gate);
    cudaGetSymbolAddress((void**)&normed, g_normed);
    cudaGetSymbolAddress((void**)&g1, g_g1);
    cudaGetSymbolAddress((void**)&lam, g_lam);
    cudaGetSymbolAddress((void**)&gam, g_gam);

    dim3 gFull(DDIM / 128, MTOK / 128);   // (8, 32)
    dim3 gG1(1, MTOK / 128);              // N = 64 -> one block column

    tgemm_k<<<gFull, 256>>>(x, Wq, q, DDIM, DDIM, 1);        // q = silu(x@Wq)
    tgemm_k<<<gFull, 256>>>(x, Wk, k, DDIM, DDIM, 1);        // k = silu(x@Wk)
    tgemm_k<<<gFull, 256>>>(x, Wv, v, DDIM, DDIM, 1);        // v = silu(x@Wv)
    k_fgamma<<<MTOK / 32, 256>>>(x, Wf, Wgamma, lam, gam);   // lam, gamma
    k_norm_a<<<MTOK, 512>>>(k, lam, gam, a);                 // k := l2norm(k); a = k*gam*lam
    k_scan<<<128, 128>>>(q, k, v, a, lam, attn);             // delta-rule recurrence
    tgemm_k<<<gG1, 256>>>(x, Wg1, g1, 64, DDIM, 0);          // g1 = x@Wg1
    tgemm_k<<<gFull, 256>>>(g1, Wg2, gate, DDIM, 64, 2);     // gate = sigmoid(g1@Wg2)
    k_ln<<<MTOK, 256>>>(attn, gate, nw, normed);             // gated + LayerNorm
    tgemm_k<<<gFull, 256>>>(normed, Wo, out, DDIM, DDIM, 0); // out = normed@Wo
}

// round 4
// speedup vs baseline: 1.8466x; 1.6945x over previous
#include <cuda_runtime.h>
#include <cuda_fp16.h>
#include <math.h>
#include <stdint.h>

#define MTOK 4096   // B*N
#define DDIM 1024
#define NHEAD 16
#define SEQ 2048
#define TS 16

// ---------------- scratch (device globals; no allocs allowed) ----------------
static __device__ float g_q[MTOK * DDIM];
static __device__ float g_k[MTOK * DDIM];
static __device__ float g_v[MTOK * DDIM];
static __device__ float g_a[MTOK * DDIM];
static __device__ float g_attn[MTOK * DDIM];
static __device__ float g_gate[MTOK * DDIM];
static __device__ float g_lam[MTOK * NHEAD];
static __device__ float g_gam[MTOK * NHEAD];
static __device__ __half g_xh[MTOK * DDIM];
static __device__ __half g_g1h[MTOK * 64];
static __device__ __half g_normedh[MTOK * DDIM];
static __device__ __half g_wqt[DDIM * DDIM];
static __device__ __half g_wkt[DDIM * DDIM];
static __device__ __half g_wvt[DDIM * DDIM];
static __device__ __half g_wot[DDIM * DDIM];
static __device__ __half g_wg1t[64 * DDIM];
static __device__ __half g_wg2t[DDIM * 64];

__device__ __forceinline__ uint32_t smem_u32(const void* p) {
    uint32_t a;
    asm("{ .reg .u64 t; cvta.to.shared.u64 t, %1; cvt.u32.u64 %0, t; }" : "=r"(a) : "l"(p));
    return a;
}
__device__ __forceinline__ void cp16(uint32_t dst, const void* src, int valid) {
    int sz = valid ? 16 : 0;
    asm volatile("cp.async.cg.shared.global [%0], [%1], 16, %2;" :: "r"(dst), "l"(src), "r"(sz));
}

// ================= fp16 tensor-core GEMM: C = act(A @ Bt^T) =================
// A: M x K row-major half. Bt: Ntot x K row-major half. C: M x Ntot (f32 or f16).
// Tile 128x128, K-tile 32, 3-stage cp.async. 256 threads = 8 warps (2x4),
// warp tile 64x32, mma.sync.m16n8k16.f16. Rows padded to 80B -> conflict-free.
// act: 0 none, 1 silu, 2 sigmoid. outHalf: write __half C instead of float.
#define ROWB 80
#define STAGEB (128 * ROWB * 2)          // A(10240)+B(10240)
#define HG_SMEM (3 * STAGEB)             // 61440

__global__ __launch_bounds__(256, 1)
void hgemm(const __half* __restrict__ A, const __half* __restrict__ Bt,
           void* __restrict__ Cout, int Ntot, int K, int act, int outHalf)
{
    extern __shared__ __align__(128) char smem[];
    const uint32_t sb = smem_u32(smem);
    const int tid = threadIdx.x, lane = tid & 31, warp = tid >> 5;
    const int wm = warp >> 2, wn = warp & 3;     // 2 x 4 warps
    const int g = lane >> 2, tig = lane & 3;
    const int m0 = blockIdx.y * 128, n0 = blockIdx.x * 128;
    const int NC = K >> 5;

    float acc[4][4][4];
#pragma unroll
    for (int mt = 0; mt < 4; ++mt)
#pragma unroll
        for (int nt = 0; nt < 4; ++nt)
#pragma unroll
            for (int j = 0; j < 4; ++j) acc[mt][nt][j] = 0.f;

#define LOAD_TILE(kt, ss) do { \
    uint32_t aB = sb + (ss) * STAGEB; \
    uint32_t bB = aB + 128 * ROWB; \
    _Pragma("unroll") \
    for (int i = 0; i < 2; ++i) { \
        int id = tid + i * 256; \
        int r = id >> 2, c = id & 3; \
        cp16(aB + r * ROWB + c * 16, A + (size_t)(m0 + r) * K + (kt) * 32 + c * 8, 1); \
        int nr = n0 + r; int ok = nr < Ntot; int nrc = ok ? nr : 0; \
        cp16(bB + r * ROWB + c * 16, Bt + (size_t)nrc * K + (kt) * 32 + c * 8, ok); \
    } \
} while (0)

#pragma unroll
    for (int p = 0; p < 2; ++p) {
        if (p < NC) LOAD_TILE(p, p);
        asm volatile("cp.async.commit_group;" ::: "memory");
    }

    for (int kt = 0; kt < NC; ++kt) {
        asm volatile("cp.async.wait_group 1;" ::: "memory");
        __syncthreads();
        int ln = kt + 2;
        if (ln < NC) {
            int sl = ln - (ln / 3) * 3;
            LOAD_TILE(ln, sl);
        }
        asm volatile("cp.async.commit_group;" ::: "memory");

        int st = kt - (kt / 3) * 3;
        uint32_t aB = sb + st * STAGEB;
        uint32_t bB = aB + 128 * ROWB;
#pragma unroll
        for (int s = 0; s < 2; ++s) {
            uint32_t af[4][4], bf[4][2];
#pragma unroll
            for (int mt = 0; mt < 4; ++mt) {
                uint32_t addr = aB + (wm * 64 + mt * 16 + (lane & 15)) * ROWB
                              + (2 * s + (lane >> 4)) * 16;
                asm volatile("ldmatrix.sync.aligned.m8n8.x4.shared.b16 {%0,%1,%2,%3}, [%4];"
                    : "=r"(af[mt][0]), "=r"(af[mt][1]), "=r"(af[mt][2]), "=r"(af[mt][3])
                    : "r"(addr));
            }
#pragma unroll
            for (int nt = 0; nt < 4; ++nt) {
                uint32_t addr = bB + (wn * 32 + nt * 8 + (lane & 7)) * ROWB
                              + (2 * s + ((lane >> 3) & 1)) * 16;
                asm volatile("ldmatrix.sync.aligned.m8n8.x2.shared.b16 {%0,%1}, [%2];"
                    : "=r"(bf[nt][0]), "=r"(bf[nt][1]) : "r"(addr));
            }
#pragma unroll
            for (int mt = 0; mt < 4; ++mt)
#pragma unroll
                for (int nt = 0; nt < 4; ++nt) {
                    asm volatile(
                        "mma.sync.aligned.m16n8k16.row.col.f32.f16.f16.f32 "
                        "{%0,%1,%2,%3}, {%4,%5,%6,%7}, {%8,%9}, {%0,%1,%2,%3};"
                        : "+f"(acc[mt][nt][0]), "+f"(acc[mt][nt][1]),
                          "+f"(acc[mt][nt][2]), "+f"(acc[mt][nt][3])
                        : "r"(af[mt][0]), "r"(af[mt][1]), "r"(af[mt][2]), "r"(af[mt][3]),
                          "r"(bf[nt][0]), "r"(bf[nt][1]));
                }
        }
        __syncthreads();
    }
#undef LOAD_TILE

    // epilogue
    float* Cf = (float*)Cout;
    __half* Ch = (__half*)Cout;
#pragma unroll
    for (int mt = 0; mt < 4; ++mt) {
        int row = m0 + wm * 64 + mt * 16 + g;
#pragma unroll
        for (int nt = 0; nt < 4; ++nt) {
            int col = n0 + wn * 32 + nt * 8 + tig * 2;
            if (col < Ntot) {
                float c0 = acc[mt][nt][0], c1 = acc[mt][nt][1];
                float c2 = acc[mt][nt][2], c3 = acc[mt][nt][3];
                if (act == 1) {
                    c0 = c0 / (1.f + expf(-c0)); c1 = c1 / (1.f + expf(-c1));
                    c2 = c2 / (1.f + expf(-c2)); c3 = c3 / (1.f + expf(-c3));
                } else if (act == 2) {
                    c0 = 1.f / (1.f + expf(-c0)); c1 = 1.f / (1.f + expf(-c1));
                    c2 = 1.f / (1.f + expf(-c2)); c3 = 1.f / (1.f + expf(-c3));
                }
                if (outHalf) {
                    *(__half2*)&Ch[(size_t)row * Ntot + col]       = __floats2half2_rn(c0, c1);
                    *(__half2*)&Ch[(size_t)(row + 8) * Ntot + col] = __floats2half2_rn(c2, c3);
                } else {
                    *(float2*)&Cf[(size_t)row * Ntot + col]       = make_float2(c0, c1);
                    *(float2*)&Cf[(size_t)(row + 8) * Ntot + col] = make_float2(c2, c3);
                }
            }
        }
    }
}

// ================= float -> half =================
__global__ void k_f2h(const float* __restrict__ S, __half* __restrict__ D, int n)
{
    int i = (blockIdx.x * 256 + threadIdx.x) * 4;
    if (i < n) {
        float4 f = *(const float4*)&S[i];
        __half2 h0 = __floats2half2_rn(f.x, f.y);
        __half2 h1 = __floats2half2_rn(f.z, f.w);
        *(__half2*)&D[i]     = h0;
        *(__half2*)&D[i + 2] = h1;
    }
}

// ================= transpose+convert: D[C x R] (half) = S[R x C]^T =================
__global__ void k_tr(const float* __restrict__ S, __half* __restrict__ D, int R, int C)
{
    __shared__ float t[32][33];
    int c0 = blockIdx.x * 32, r0 = blockIdx.y * 32;
    int x = threadIdx.x, y = threadIdx.y;   // 32 x 8
#pragma unroll
    for (int i = 0; i < 32; i += 8) t[y + i][x] = S[(size_t)(r0 + y + i) * C + c0 + x];
    __syncthreads();
#pragma unroll
    for (int i = 0; i < 32; i += 8)
        D[(size_t)(c0 + y + i) * R + r0 + x] = __float2half_rn(t[x][y + i]);
}

// ================= per-token f / gamma projections (fp32) =================
__global__ void k_fgamma(const float* __restrict__ x, const float* __restrict__ Wf,
                         const float* __restrict__ Wg, float* __restrict__ lam,
                         float* __restrict__ gam)
{
    __shared__ float xs[16][33];
    __shared__ float Ws[32][32];
    int t0 = blockIdx.x * 16;
    int tid = threadIdx.x;      // 256
    int c = tid & 31, tg = tid >> 5;
    float acc[2] = {0.f, 0.f};

    for (int k0 = 0; k0 < DDIM; k0 += 32) {
        __syncthreads();
#pragma unroll
        for (int i = 0; i < 2; ++i) {
            int idx = tid + i * 256;
            int tt = idx >> 5, kk = idx & 31;
            xs[tt][kk] = x[(size_t)(t0 + tt) * DDIM + k0 + kk];
        }
#pragma unroll
        for (int i = 0; i < 4; ++i) {
            int idx = tid + i * 256;
            int kr = idx >> 5, col = idx & 31;
            Ws[kr][col] = (col < 16) ? Wf[(k0 + kr) * NHEAD + col]
                                     : Wg[(k0 + kr) * NHEAD + (col - 16)];
        }
        __syncthreads();
#pragma unroll 8
        for (int kk = 0; kk < 32; ++kk) {
            float w = Ws[kk][c];
            acc[0] = fmaf(xs[tg * 2][kk], w, acc[0]);
            acc[1] = fmaf(xs[tg * 2 + 1][kk], w, acc[1]);
        }
    }
#pragma unroll
    for (int i = 0; i < 2; ++i) {
        int t = t0 + tg * 2 + i;
        float sg = 1.f / (1.f + expf(-acc[i]));
        if (c < 16) lam[t * NHEAD + c] = sg;
        else        gam[t * NHEAD + (c - 16)] = -sg;
    }
}

// ================= l2norm(k) per head; a = k_norm * gamma * lambda =================
__global__ void k_norm_a(float* __restrict__ k, const float* __restrict__ lam,
                         const float* __restrict__ gam, float* __restrict__ a)
{
    int t = blockIdx.x;
    int w = threadIdx.x >> 5;
    int lane = threadIdx.x & 31;
    int base = t * DDIM + w * 64;
    float k0 = k[base + lane], k1 = k[base + lane + 32];
    float ss = k0 * k0 + k1 * k1;
#pragma unroll
    for (int o = 16; o; o >>= 1) ss += __shfl_xor_sync(0xffffffffu, ss, o);
    float inv = 1.f / fmaxf(sqrtf(ss), 1e-12f);
    float c = gam[t * NHEAD + w] * lam[t * NHEAD + w];
    float kn0 = k0 * inv, kn1 = k1 * inv;
    k[base + lane] = kn0;       k[base + lane + 32] = kn1;
    a[base + lane] = kn0 * c;   a[base + lane + 32] = kn1 * c;
}

// ================= delta-rule scan (32 cols x 4 subs per block) =================
__global__ void k_scan(const float* __restrict__ q, const float* __restrict__ k,
                       const float* __restrict__ v, const float* __restrict__ a,
                       const float* __restrict__ lamArr, float* __restrict__ o)
{
    __shared__ __align__(16) float qs[TS][64];
    __shared__ __align__(16) float ks[TS][64];
    __shared__ __align__(16) float as_[TS][64];
    __shared__ float vs[TS][32];
    __shared__ float lm[TS];

    int blk = blockIdx.x;           // 0..63
    int bh = blk >> 1;
    int half = blk & 1;
    int b = bh >> 4, h = bh & 15;
    int tid = threadIdx.x;          // 0..127
    int col = tid >> 2;             // 0..31
    int sub = tid & 3;
    int tok0 = b * SEQ;
    int hoff = h * 64;

    float s[16];
#pragma unroll
    for (int j = 0; j < 16; ++j) s[j] = 0.f;

    for (int st = 0; st < SEQ / TS; ++st) {
        __syncthreads();
        int tb = tok0 + st * TS;
#pragma unroll
        for (int i = 0; i < 8; ++i) { int id = tid + i * 128; int tt = id >> 6, cc = id & 63;
            qs[tt][cc] = q[(size_t)(tb + tt) * DDIM + hoff + cc]; }
#pragma unroll
        for (int i = 0; i < 8; ++i) { int id = tid + i * 128; int tt = id >> 6, cc = id & 63;
            ks[tt][cc] = k[(size_t)(tb + tt) * DDIM + hoff + cc]; }
#pragma unroll
        for (int i = 0; i < 8; ++i) { int id = tid + i * 128; int tt = id >> 6, cc = id & 63;
            as_[tt][cc] = a[(size_t)(tb + tt) * DDIM + hoff + cc]; }
#pragma unroll
        for (int i = 0; i < 4; ++i) { int id = tid + i * 128; int tt = id >> 5, cl = id & 31;
            vs[tt][cl] = v[(size_t)(tb + tt) * DDIM + hoff + half * 32 + cl]; }
        if (tid < TS) lm[tid] = lamArr[(tb + tid) * NHEAD + h];
        __syncthreads();

#pragma unroll 4
        for (int tt = 0; tt < TS; ++tt) {
            float l = lm[tt];
            float4 a0 = *(const float4*)&as_[tt][sub * 16];
            float4 a1 = *(const float4*)&as_[tt][sub * 16 + 4];
            float4 a2 = *(const float4*)&as_[tt][sub * 16 + 8];
            float4 a3 = *(const float4*)&as_[tt][sub * 16 + 12];
            float sp[16];
#pragma unroll
            for (int j = 0; j < 16; ++j) sp[j] = s[j] * l;
            float u0 = a0.x * sp[0] + a0.y * sp[1] + a0.z * sp[2] + a0.w * sp[3];
            float u1 = a1.x * sp[4] + a1.y * sp[5] + a1.z * sp[6] + a1.w * sp[7];
            float u2 = a2.x * sp[8] + a2.y * sp[9] + a2.z * sp[10] + a2.w * sp[11];
            float u3 = a3.x * sp[12] + a3.y * sp[13] + a3.z * sp[14] + a3.w * sp[15];
            float up = (u0 + u1) + (u2 + u3);
            up += __shfl_xor_sync(0xffffffffu, up, 1);
            up += __shfl_xor_sync(0xffffffffu, up, 2);
            float u = up + vs[tt][col];
            float4 k0 = *(const float4*)&ks[tt][sub * 16];
            float4 k1 = *(const float4*)&ks[tt][sub * 16 + 4];
            float4 k2 = *(const float4*)&ks[tt][sub * 16 + 8];
            float4 k3 = *(const float4*)&ks[tt][sub * 16 + 12];
            s[0] = fmaf(k0.x, u, sp[0]);  s[1] = fmaf(k0.y, u, sp[1]);
            s[2] = fmaf(k0.z, u, sp[2]);  s[3] = fmaf(k0.w, u, sp[3]);
            s[4] = fmaf(k1.x, u, sp[4]);  s[5] = fmaf(k1.y, u, sp[5]);
            s[6] = fmaf(k1.z, u, sp[6]);  s[7] = fmaf(k1.w, u, sp[7]);
            s[8] = fmaf(k2.x, u, sp[8]);  s[9] = fmaf(k2.y, u, sp[9]);
            s[10] = fmaf(k2.z, u, sp[10]); s[11] = fmaf(k2.w, u, sp[11]);
            s[12] = fmaf(k3.x, u, sp[12]); s[13] = fmaf(k3.w == k3.w ? k3.y : k3.y, u, sp[13]);
            s[14] = fmaf(k3.z, u, sp[14]); s[15] = fmaf(k3.w, u, sp[15]);
            float4 q0 = *(const float4*)&qs[tt][sub * 16];
            float4 q1 = *(const float4*)&qs[tt][sub * 16 + 4];
            float4 q2 = *(const float4*)&qs[tt][sub * 16 + 8];
            float4 q3 = *(const float4*)&qs[tt][sub * 16 + 12];
            float o0 = q0.x * s[0] + q0.y * s[1] + q0.z * s[2] + q0.w * s[3];
            float o1 = q1.x * s[4] + q1.y * s[5] + q1.z * s[6] + q1.w * s[7];
            float o2 = q2.x * s[8] + q2.y * s[9] + q2.z * s[10] + q2.w * s[11];
            float o3 = q3.x * s[12] + q3.y * s[13] + q3.z * s[14] + q3.w * s[15];
            float op = (o0 + o1) + (o2 + o3);
            op += __shfl_xor_sync(0xffffffffu, op, 1);
            op += __shfl_xor_sync(0xffffffffu, op, 2);
            if (sub == 0)
                o[(size_t)(tb + tt) * DDIM + hoff + half * 32 + col] = op;
        }
    }
}

// ================= gate-multiply + LayerNorm -> half =================
__global__ void k_ln(const float* __restrict__ attn, const float* __restrict__ gate,
                     const float* __restrict__ nw, __half* __restrict__ outh)
{
    __shared__ float red[32];
    int t = blockIdx.x;
    int tid = threadIdx.x;  // 256
    int lane = tid & 31, w = tid >> 5;
    float y[4];
    float sm = 0.f;
#pragma unroll
    for (int i = 0; i < 4; ++i) {
        int j = tid + i * 256;
        y[i] = attn[(size_t)t * DDIM + j] * gate[(size_t)t * DDIM + j];
        sm += y[i];
    }
#pragma unroll
    for (int o = 16; o; o >>= 1) sm += __shfl_xor_sync(0xffffffffu, sm, o);
    if (lane == 0) red[w] = sm;
    __syncthreads();
    if (w == 0) {
        float v2 = (lane < 8) ? red[lane] : 0.f;
#pragma unroll
        for (int o = 4; o; o >>= 1) v2 += __shfl_xor_sync(0xffffffffu, v2, o);
        if (lane == 0) red[0] = v2;
    }
    __syncthreads();
    float mu = red[0] * (1.f / DDIM);
    __syncthreads();
    float vsum = 0.f;
#pragma unroll
    for (int i = 0; i < 4; ++i) { float d = y[i] - mu; vsum += d * d; }
#pragma unroll
    for (int o = 16; o; o >>= 1) vsum += __shfl_xor_sync(0xffffffffu, vsum, o);
    if (lane == 0) red[w] = vsum;
    __syncthreads();
    if (w == 0) {
        float v2 = (lane < 8) ? red[lane] : 0.f;
#pragma unroll
        for (int o = 4; o; o >>= 1) v2 += __shfl_xor_sync(0xffffffffu, v2, o);
        if (lane == 0) red[0] = v2;
    }
    __syncthreads();
    float inv = rsqrtf(red[0] * (1.f / DDIM) + 1e-5f);
#pragma unroll
    for (int i = 0; i < 4; ++i) {
        int j = tid + i * 256;
        outh[(size_t)t * DDIM + j] = __float2half_rn((y[i] - mu) * inv * nw[j]);
    }
}

// ================= launch =================
extern "C" void kernel_launch(void* const* d_in, const int* in_sizes, int n_in,
                              void* d_out, int out_size)
{
    const float* x      = (const float*)d_in[0];
    const float* Wq     = (const float*)d_in[1];
    const float* Wk     = (const float*)d_in[2];
    const float* Wv     = (const float*)d_in[3];
    const float* Wgamma = (const float*)d_in[4];
    const float* Wf     = (const float*)d_in[5];
    const float* Wg1    = (const float*)d_in[6];
    const float* Wg2    = (const float*)d_in[7];
    const float* Wo     = (const float*)d_in[8];
    const float* nw     = (const float*)d_in[9];
    float* out = (float*)d_out;

    float *q, *k, *v, *a, *attn, *gate, *lam, *gam;
    __half *xh, *g1h, *normedh, *wqt, *wkt, *wvt, *wot, *wg1t, *wg2t;
    cudaGetSymbolAddress((void**)&q, g_q);
    cudaGetSymbolAddress((void**)&k, g_k);
    cudaGetSymbolAddress((void**)&v, g_v);
    cudaGetSymbolAddress((void**)&a, g_a);
    cudaGetSymbolAddress((void**)&attn, g_attn);
    cudaGetSymbolAddress((void**)&gate, g_gate);
    cudaGetSymbolAddress((void**)&lam, g_lam);
    cudaGetSymbolAddress((void**)&gam, g_gam);
    cudaGetSymbolAddress((void**)&xh, g_xh);
    cudaGetSymbolAddress((void**)&g1h, g_g1h);
    cudaGetSymbolAddress((void**)&normedh, g_normedh);
    cudaGetSymbolAddress((void**)&wqt, g_wqt);
    cudaGetSymbolAddress((void**)&wkt, g_wkt);
    cudaGetSymbolAddress((void**)&wvt, g_wvt);
    cudaGetSymbolAddress((void**)&wot, g_wot);
    cudaGetSymbolAddress((void**)&wg1t, g_wg1t);
    cudaGetSymbolAddress((void**)&wg2t, g_wg2t);

    cudaFuncSetAttribute(hgemm, cudaFuncAttributeMaxDynamicSharedMemorySize, HG_SMEM);

    dim3 trBlk(32, 8);
    k_f2h<<<MTOK * DDIM / (256 * 4), 256>>>(x, xh, MTOK * DDIM);
    k_tr<<<dim3(32, 32), trBlk>>>(Wq, wqt, DDIM, DDIM);
    k_tr<<<dim3(32, 32), trBlk>>>(Wk, wkt, DDIM, DDIM);
    k_tr<<<dim3(32, 32), trBlk>>>(Wv, wvt, DDIM, DDIM);
    k_tr<<<dim3(32, 32), trBlk>>>(Wo, wot, DDIM, DDIM);
    k_tr<<<dim3(2, 32), trBlk>>>(Wg1, wg1t, DDIM, 64);   // -> 64 x 1024
    k_tr<<<dim3(32, 2), trBlk>>>(Wg2, wg2t, 64, DDIM);   // -> 1024 x 64

    dim3 gFull(8, 32);   // N=1024, M=4096
    dim3 gG1(1, 32);     // N=64

    hgemm<<<gFull, 256, HG_SMEM>>>(xh, wqt, q, DDIM, DDIM, 1, 0);       // q = silu
    hgemm<<<gFull, 256, HG_SMEM>>>(xh, wkt, k, DDIM, DDIM, 1, 0);       // k = silu
    hgemm<<<gFull, 256, HG_SMEM>>>(xh, wvt, v, DDIM, DDIM, 1, 0);       // v = silu
    k_fgamma<<<MTOK / 16, 256>>>(x, Wf, Wgamma, lam, gam);
    k_norm_a<<<MTOK, 512>>>(k, lam, gam, a);
    k_scan<<<64, 128>>>(q, k, v, a, lam, attn);
    hgemm<<<gG1, 256, HG_SMEM>>>(xh, wg1t, g1h, 64, DDIM, 0, 1);        // g1 (half)
    hgemm<<<gFull, 256, HG_SMEM>>>(g1h, wg2t, gate, DDIM, 64, 2, 0);    // gate = sigmoid
    k_ln<<<MTOK, 256>>>(attn, gate, nw, normedh);                       // LN -> half
    hgemm<<<gFull, 256, HG_SMEM>>>(normedh, wot, out, DDIM, DDIM, 0, 0);
}

// round 5
// speedup vs baseline: 2.2003x; 1.1916x over previous
#include <cuda_runtime.h>
#include <cuda_fp16.h>
#include <math.h>
#include <stdint.h>

#define MTOK 4096   // B*N
#define DDIM 1024
#define NHEAD 16
#define SEQ 2048
#define TS 16
#define QSTR 3072   // fused qkv row stride

// ---------------- scratch (device globals; no allocs allowed) ----------------
static __device__ float g_qkv[MTOK * QSTR];      // [q | k | v] fused
static __device__ float g_a[MTOK * DDIM];
static __device__ float g_attn[MTOK * DDIM];
static __device__ float g_gate[MTOK * DDIM];
static __device__ float g_lam[MTOK * NHEAD];
static __device__ float g_gam[MTOK * NHEAD];
static __device__ __half g_xh[MTOK * DDIM];
static __device__ __half g_g1h[MTOK * 64];
static __device__ __half g_normedh[MTOK * DDIM];
static __device__ __half g_wqkvt[3 * DDIM * DDIM];
static __device__ __half g_wot[DDIM * DDIM];
static __device__ __half g_wg1t[64 * DDIM];
static __device__ __half g_wg2t[DDIM * 64];

__device__ __forceinline__ uint32_t smem_u32(const void* p) {
    uint32_t a;
    asm("{ .reg .u64 t; cvta.to.shared.u64 t, %1; cvt.u32.u64 %0, t; }" : "=r"(a) : "l"(p));
    return a;
}
__device__ __forceinline__ void cp16(uint32_t dst, const void* src, int valid) {
    int sz = valid ? 16 : 0;
    asm volatile("cp.async.cg.shared.global [%0], [%1], 16, %2;" :: "r"(dst), "l"(src), "r"(sz));
}

// ================= fp16 tensor-core GEMM: C = act(A @ Bt^T) =================
// A: M x K half. Bt: Ntot x K half. C: M x Ntot (f32 or f16), row stride Ntot.
// Tile 128x128, K-tile 32, 4-stage cp.async (3-ahead). 256 threads = 8 warps (2x4),
// warp tile 64x32, mma.sync.m16n8k16. Rows padded to 80B -> conflict-free ldmatrix.
#define ROWB 80
#define STAGEB (128 * ROWB * 2)          // A(10240)+B(10240) = 20480
#define HG_SMEM (4 * STAGEB)             // 81920

__global__ __launch_bounds__(256, 1)
void hgemm(const __half* __restrict__ A, const __half* __restrict__ Bt,
           void* __restrict__ Cout, int Ntot, int K, int act, int outHalf)
{
    extern __shared__ __align__(128) char smem[];
    const uint32_t sb = smem_u32(smem);
    const int tid = threadIdx.x, lane = tid & 31, warp = tid >> 5;
    const int wm = warp >> 2, wn = warp & 3;
    const int g = lane >> 2, tig = lane & 3;
    const int m0 = blockIdx.y * 128, n0 = blockIdx.x * 128;
    const int NC = K >> 5;

    float acc[4][4][4];
#pragma unroll
    for (int mt = 0; mt < 4; ++mt)
#pragma unroll
        for (int nt = 0; nt < 4; ++nt)
#pragma unroll
            for (int j = 0; j < 4; ++j) acc[mt][nt][j] = 0.f;

#define LOAD_TILE(kt, ss) do { \
    uint32_t aB = sb + (ss) * STAGEB; \
    uint32_t bB = aB + 128 * ROWB; \
    _Pragma("unroll") \
    for (int i = 0; i < 2; ++i) { \
        int id = tid + i * 256; \
        int r = id >> 2, c = id & 3; \
        cp16(aB + r * ROWB + c * 16, A + (size_t)(m0 + r) * K + (kt) * 32 + c * 8, 1); \
        int nr = n0 + r; int ok = nr < Ntot; int nrc = ok ? nr : 0; \
        cp16(bB + r * ROWB + c * 16, Bt + (size_t)nrc * K + (kt) * 32 + c * 8, ok); \
    } \
} while (0)

#pragma unroll
    for (int p = 0; p < 3; ++p) {
        if (p < NC) LOAD_TILE(p, p);
        asm volatile("cp.async.commit_group;" ::: "memory");
    }

    for (int kt = 0; kt < NC; ++kt) {
        asm volatile("cp.async.wait_group 2;" ::: "memory");
        __syncthreads();
        int ln = kt + 3;
        if (ln < NC) LOAD_TILE(ln, ln & 3);
        asm volatile("cp.async.commit_group;" ::: "memory");

        uint32_t aB = sb + (kt & 3) * STAGEB;
        uint32_t bB = aB + 128 * ROWB;
#pragma unroll
        for (int s = 0; s < 2; ++s) {
            uint32_t af[4][4], bf[4][2];
#pragma unroll
            for (int mt = 0; mt < 4; ++mt) {
                uint32_t addr = aB + (wm * 64 + mt * 16 + (lane & 15)) * ROWB
                              + (2 * s + (lane >> 4)) * 16;
                asm volatile("ldmatrix.sync.aligned.m8n8.x4.shared.b16 {%0,%1,%2,%3}, [%4];"
                    : "=r"(af[mt][0]), "=r"(af[mt][1]), "=r"(af[mt][2]), "=r"(af[mt][3])
                    : "r"(addr));
            }
#pragma unroll
            for (int nt = 0; nt < 4; ++nt) {
                uint32_t addr = bB + (wn * 32 + nt * 8 + (lane & 7)) * ROWB
                              + (2 * s + ((lane >> 3) & 1)) * 16;
                asm volatile("ldmatrix.sync.aligned.m8n8.x2.shared.b16 {%0,%1}, [%2];"
                    : "=r"(bf[nt][0]), "=r"(bf[nt][1]) : "r"(addr));
            }
#pragma unroll
            for (int mt = 0; mt < 4; ++mt)
#pragma unroll
                for (int nt = 0; nt < 4; ++nt) {
                    asm volatile(
                        "mma.sync.aligned.m16n8k16.row.col.f32.f16.f16.f32 "
                        "{%0,%1,%2,%3}, {%4,%5,%6,%7}, {%8,%9}, {%0,%1,%2,%3};"
                        : "+f"(acc[mt][nt][0]), "+f"(acc[mt][nt][1]),
                          "+f"(acc[mt][nt][2]), "+f"(acc[mt][nt][3])
                        : "r"(af[mt][0]), "r"(af[mt][1]), "r"(af[mt][2]), "r"(af[mt][3]),
                          "r"(bf[nt][0]), "r"(bf[nt][1]));
                }
        }
        __syncthreads();
    }
#undef LOAD_TILE

    float* Cf = (float*)Cout;
    __half* Ch = (__half*)Cout;
#pragma unroll
    for (int mt = 0; mt < 4; ++mt) {
        int row = m0 + wm * 64 + mt * 16 + g;
#pragma unroll
        for (int nt = 0; nt < 4; ++nt) {
            int col = n0 + wn * 32 + nt * 8 + tig * 2;
            if (col < Ntot) {
                float c0 = acc[mt][nt][0], c1 = acc[mt][nt][1];
                float c2 = acc[mt][nt][2], c3 = acc[mt][nt][3];
                if (act == 1) {
                    c0 = c0 / (1.f + expf(-c0)); c1 = c1 / (1.f + expf(-c1));
                    c2 = c2 / (1.f + expf(-c2)); c3 = c3 / (1.f + expf(-c3));
                } else if (act == 2) {
                    c0 = 1.f / (1.f + expf(-c0)); c1 = 1.f / (1.f + expf(-c1));
                    c2 = 1.f / (1.f + expf(-c2)); c3 = 1.f / (1.f + expf(-c3));
                }
                if (outHalf) {
                    *(__half2*)&Ch[(size_t)row * Ntot + col]       = __floats2half2_rn(c0, c1);
                    *(__half2*)&Ch[(size_t)(row + 8) * Ntot + col] = __floats2half2_rn(c2, c3);
                } else {
                    *(float2*)&Cf[(size_t)row * Ntot + col]       = make_float2(c0, c1);
                    *(float2*)&Cf[(size_t)(row + 8) * Ntot + col] = make_float2(c2, c3);
                }
            }
        }
    }
}

// ================= float -> half =================
__global__ void k_f2h(const float* __restrict__ S, __half* __restrict__ D, int n)
{
    int i = (blockIdx.x * 256 + threadIdx.x) * 4;
    if (i < n) {
        float4 f = *(const float4*)&S[i];
        *(__half2*)&D[i]     = __floats2half2_rn(f.x, f.y);
        *(__half2*)&D[i + 2] = __floats2half2_rn(f.z, f.w);
    }
}

// ================= all weight transposes+convert in ONE launch =================
// Wq/Wk/Wv -> wqkvt (3072 x 1024), Wo -> wot, Wg1 -> wg1t (64x1024), Wg2 -> wg2t (1024x64)
__global__ void k_tr_all(const float* __restrict__ Wq, const float* __restrict__ Wk,
                         const float* __restrict__ Wv, const float* __restrict__ Wo,
                         const float* __restrict__ Wg1, const float* __restrict__ Wg2,
                         __half* __restrict__ wqkvt, __half* __restrict__ wot,
                         __half* __restrict__ wg1t, __half* __restrict__ wg2t)
{
    __shared__ float t[32][33];
    int blk = blockIdx.x;
    const float* S; __half* D; int R, C, tile;
    if (blk < 3072) {
        int seg = blk >> 10; tile = blk & 1023;
        S = (seg == 0) ? Wq : (seg == 1) ? Wk : Wv;
        D = wqkvt + (size_t)seg * DDIM * DDIM; R = DDIM; C = DDIM;
    } else if (blk < 4096) { tile = blk - 3072; S = Wo;  D = wot;  R = DDIM; C = DDIM; }
    else if (blk < 4160)   { tile = blk - 4096; S = Wg1; D = wg1t; R = DDIM; C = 64; }
    else                   { tile = blk - 4160; S = Wg2; D = wg2t; R = 64;   C = DDIM; }
    int tiles_x = C >> 5;
    int c0 = (tile % tiles_x) * 32, r0 = (tile / tiles_x) * 32;
    int x = threadIdx.x, y = threadIdx.y;   // 32 x 8
#pragma unroll
    for (int i = 0; i < 32; i += 8) t[y + i][x] = S[(size_t)(r0 + y + i) * C + c0 + x];
    __syncthreads();
#pragma unroll
    for (int i = 0; i < 32; i += 8)
        D[(size_t)(c0 + y + i) * R + r0 + x] = __float2half_rn(t[x][y + i]);
}

// ================= per-token f / gamma projections (fp32) =================
__global__ void k_fgamma(const float* __restrict__ x, const float* __restrict__ Wf,
                         const float* __restrict__ Wg, float* __restrict__ lam,
                         float* __restrict__ gam)
{
    __shared__ float xs[16][33];
    __shared__ float Ws[32][32];
    int t0 = blockIdx.x * 16;
    int tid = threadIdx.x;      // 256
    int c = tid & 31, tg = tid >> 5;
    float acc[2] = {0.f, 0.f};

    for (int k0 = 0; k0 < DDIM; k0 += 32) {
        __syncthreads();
#pragma unroll
        for (int i = 0; i < 2; ++i) {
            int idx = tid + i * 256;
            int tt = idx >> 5, kk = idx & 31;
            xs[tt][kk] = x[(size_t)(t0 + tt) * DDIM + k0 + kk];
        }
#pragma unroll
        for (int i = 0; i < 4; ++i) {
            int idx = tid + i * 256;
            int kr = idx >> 5, col = idx & 31;
            Ws[kr][col] = (col < 16) ? Wf[(k0 + kr) * NHEAD + col]
                                     : Wg[(k0 + kr) * NHEAD + (col - 16)];
        }
        __syncthreads();
#pragma unroll 8
        for (int kk = 0; kk < 32; ++kk) {
            float w = Ws[kk][c];
            acc[0] = fmaf(xs[tg * 2][kk], w, acc[0]);
            acc[1] = fmaf(xs[tg * 2 + 1][kk], w, acc[1]);
        }
    }
#pragma unroll
    for (int i = 0; i < 2; ++i) {
        int t = t0 + tg * 2 + i;
        float sg = 1.f / (1.f + expf(-acc[i]));
        if (c < 16) lam[t * NHEAD + c] = sg;
        else        gam[t * NHEAD + (c - 16)] = -sg;
    }
}

// ================= l2norm(k in qkv) per head; a = k_norm * gamma * lambda =================
__global__ void k_norm_a(float* __restrict__ qkv, const float* __restrict__ lam,
                         const float* __restrict__ gam, float* __restrict__ a)
{
    int t = blockIdx.x;
    int w = threadIdx.x >> 5;
    int lane = threadIdx.x & 31;
    size_t kb = (size_t)t * QSTR + DDIM + w * 64;
    float k0 = qkv[kb + lane], k1 = qkv[kb + lane + 32];
    float ss = k0 * k0 + k1 * k1;
#pragma unroll
    for (int o = 16; o; o >>= 1) ss += __shfl_xor_sync(0xffffffffu, ss, o);
    float inv = 1.f / fmaxf(sqrtf(ss), 1e-12f);
    float c = gam[t * NHEAD + w] * lam[t * NHEAD + w];
    float kn0 = k0 * inv, kn1 = k1 * inv;
    qkv[kb + lane] = kn0;               qkv[kb + lane + 32] = kn1;
    size_t ab = (size_t)t * DDIM + w * 64;
    a[ab + lane] = kn0 * c;             a[ab + lane + 32] = kn1 * c;
}

// ================= delta-rule scan (32 cols x 4 subs per block) =================
// d = a.s ; u = lam*d + v ; s' = lam*s + k*u ; o = q.s'
__global__ void k_scan(const float* __restrict__ qkv, const float* __restrict__ a,
                       const float* __restrict__ lamArr, float* __restrict__ o)
{
    __shared__ __align__(16) float qs[TS][64];
    __shared__ __align__(16) float ks[TS][64];
    __shared__ __align__(16) float as_[TS][64];
    __shared__ float vs[TS][32];
    __shared__ float lm[TS];

    int blk = blockIdx.x;           // 0..63
    int bh = blk >> 1;
    int half = blk & 1;
    int b = bh >> 4, h = bh & 15;
    int tid = threadIdx.x;          // 0..127
    int col = tid >> 2;             // 0..31
    int sub = tid & 3;
    int tok0 = b * SEQ;
    int hoff = h * 64;

    float s[16];
#pragma unroll
    for (int j = 0; j < 16; ++j) s[j] = 0.f;

    for (int st = 0; st < SEQ / TS; ++st) {
        __syncthreads();
        int tb = tok0 + st * TS;
#pragma unroll
        for (int i = 0; i < 8; ++i) { int id = tid + i * 128; int tt = id >> 6, cc = id & 63;
            qs[tt][cc] = qkv[(size_t)(tb + tt) * QSTR + hoff + cc]; }
#pragma unroll
        for (int i = 0; i < 8; ++i) { int id = tid + i * 128; int tt = id >> 6, cc = id & 63;
            ks[tt][cc] = qkv[(size_t)(tb + tt) * QSTR + DDIM + hoff + cc]; }
#pragma unroll
        for (int i = 0; i < 8; ++i) { int id = tid + i * 128; int tt = id >> 6, cc = id & 63;
            as_[tt][cc] = a[(size_t)(tb + tt) * DDIM + hoff + cc]; }
#pragma unroll
        for (int i = 0; i < 4; ++i) { int id = tid + i * 128; int tt = id >> 5, cl = id & 31;
            vs[tt][cl] = qkv[(size_t)(tb + tt) * QSTR + 2 * DDIM + hoff + half * 32 + cl]; }
        if (tid < TS) lm[tid] = lamArr[(tb + tid) * NHEAD + h];
        __syncthreads();

#pragma unroll 4
        for (int tt = 0; tt < TS; ++tt) {
            float l = lm[tt];
            float4 a0 = *(const float4*)&as_[tt][sub * 16];
            float4 a1 = *(const float4*)&as_[tt][sub * 16 + 4];
            float4 a2 = *(const float4*)&as_[tt][sub * 16 + 8];
            float4 a3 = *(const float4*)&as_[tt][sub * 16 + 12];
            // d = a . s   (pre-scale form)
            float d0 = a0.x * s[0] + a0.y * s[1] + a0.z * s[2] + a0.w * s[3];
            float d1 = a1.x * s[4] + a1.y * s[5] + a1.z * s[6] + a1.w * s[7];
            float d2 = a2.x * s[8] + a2.y * s[9] + a2.z * s[10] + a2.w * s[11];
            float d3 = a3.x * s[12] + a3.y * s[13] + a3.z * s[14] + a3.w * s[15];
            float dp = (d0 + d1) + (d2 + d3);
            dp += __shfl_xor_sync(0xffffffffu, dp, 1);
            dp += __shfl_xor_sync(0xffffffffu, dp, 2);
            float u = fmaf(l, dp, vs[tt][col]);
            float4 k0 = *(const float4*)&ks[tt][sub * 16];
            float4 k1 = *(const float4*)&ks[tt][sub * 16 + 4];
            float4 k2 = *(const float4*)&ks[tt][sub * 16 + 8];
            float4 k3 = *(const float4*)&ks[tt][sub * 16 + 12];
            s[0]  = fmaf(k0.x, u, l * s[0]);  s[1]  = fmaf(k0.y, u, l * s[1]);
            s[2]  = fmaf(k0.z, u, l * s[2]);  s[3]  = fmaf(k0.w, u, l * s[3]);
            s[4]  = fmaf(k1.x, u, l * s[4]);  s[5]  = fmaf(k1.y, u, l * s[5]);
            s[6]  = fmaf(k1.z, u, l * s[6]);  s[7]  = fmaf(k1.w, u, l * s[7]);
            s[8]  = fmaf(k2.x, u, l * s[8]);  s[9]  = fmaf(k2.y, u, l * s[9]);
            s[10] = fmaf(k2.z, u, l * s[10]); s[11] = fmaf(k2.w, u, l * s[11]);
            s[12] = fmaf(k3.x, u, l * s[12]); s[13] = fmaf(k3.y, u, l * s[13]);
            s[14] = fmaf(k3.z, u, l * s[14]); s[15] = fmaf(k3.w, u, l * s[15]);
            float4 q0 = *(const float4*)&qs[tt][sub * 16];
            float4 q1 = *(const float4*)&qs[tt][sub * 16 + 4];
            float4 q2 = *(const float4*)&qs[tt][sub * 16 + 8];
            float4 q3 = *(const float4*)&qs[tt][sub * 16 + 12];
            float o0 = q0.x * s[0] + q0.y * s[1] + q0.z * s[2] + q0.w * s[3];
            float o1 = q1.x * s[4] + q1.y * s[5] + q1.z * s[6] + q1.w * s[7];
            float o2 = q2.x * s[8] + q2.y * s[9] + q2.z * s[10] + q2.w * s[11];
            float o3 = q3.x * s[12] + q3.y * s[13] + q3.z * s[14] + q3.w * s[15];
            float op = (o0 + o1) + (o2 + o3);
            op += __shfl_xor_sync(0xffffffffu, op, 1);
            op += __shfl_xor_sync(0xffffffffu, op, 2);
            if (sub == 0)
                o[(size_t)(tb + tt) * DDIM + hoff + half * 32 + col] = op;
        }
    }
}

// ================= gate-multiply + LayerNorm -> half =================
__global__ void k_ln(const float* __restrict__ attn, const float* __restrict__ gate,
                     const float* __restrict__ nw, __half* __restrict__ outh)
{
    __shared__ float red[32];
    int t = blockIdx.x;
    int tid = threadIdx.x;  // 256
    int lane = tid & 31, w = tid >> 5;
    float y[4];
    float sm = 0.f;
#pragma unroll
    for (int i = 0; i < 4; ++i) {
        int j = tid + i * 256;
        y[i] = attn[(size_t)t * DDIM + j] * gate[(size_t)t * DDIM + j];
        sm += y[i];
    }
#pragma unroll
    for (int o = 16; o; o >>= 1) sm += __shfl_xor_sync(0xffffffffu, sm, o);
    if (lane == 0) red[w] = sm;
    __syncthreads();
    if (w == 0) {
        float v2 = (lane < 8) ? red[lane] : 0.f;
#pragma unroll
        for (int o = 4; o; o >>= 1) v2 += __shfl_xor_sync(0xffffffffu, v2, o);
        if (lane == 0) red[0] = v2;
    }
    __syncthreads();
    float mu = red[0] * (1.f / DDIM);
    __syncthreads();
    float vsum = 0.f;
#pragma unroll
    for (int i = 0; i < 4; ++i) { float d = y[i] - mu; vsum += d * d; }
#pragma unroll
    for (int o = 16; o; o >>= 1) vsum += __shfl_xor_sync(0xffffffffu, vsum, o);
    if (lane == 0) red[w] = vsum;
    __syncthreads();
    if (w == 0) {
        float v2 = (lane < 8) ? red[lane] : 0.f;
#pragma unroll
        for (int o = 4; o; o >>= 1) v2 += __shfl_xor_sync(0xffffffffu, v2, o);
        if (lane == 0) red[0] = v2;
    }
    __syncthreads();
    float inv = rsqrtf(red[0] * (1.f / DDIM) + 1e-5f);
#pragma unroll
    for (int i = 0; i < 4; ++i) {
        int j = tid + i * 256;
        outh[(size_t)t * DDIM + j] = __float2half_rn((y[i] - mu) * inv * nw[j]);
    }
}

// ================= launch =================
extern "C" void kernel_launch(void* const* d_in, const int* in_sizes, int n_in,
                              void* d_out, int out_size)
{
    const float* x      = (const float*)d_in[0];
    const float* Wq     = (const float*)d_in[1];
    const float* Wk     = (const float*)d_in[2];
    const float* Wv     = (const float*)d_in[3];
    const float* Wgamma = (const float*)d_in[4];
    const float* Wf     = (const float*)d_in[5];
    const float* Wg1    = (const float*)d_in[6];
    const float* Wg2    = (const float*)d_in[7];
    const float* Wo     = (const float*)d_in[8];
    const float* nw     = (const float*)d_in[9];
    float* out = (float*)d_out;

    float *qkv, *a, *attn, *gate, *lam, *gam;
    __half *xh, *g1h, *normedh, *wqkvt, *wot, *wg1t, *wg2t;
    cudaGetSymbolAddress((void**)&qkv, g_qkv);
    cudaGetSymbolAddress((void**)&a, g_a);
    cudaGetSymbolAddress((void**)&attn, g_attn);
    cudaGetSymbolAddress((void**)&gate, g_gate);
    cudaGetSymbolAddress((void**)&lam, g_lam);
    cudaGetSymbolAddress((void**)&gam, g_gam);
    cudaGetSymbolAddress((void**)&xh, g_xh);
    cudaGetSymbolAddress((void**)&g1h, g_g1h);
    cudaGetSymbolAddress((void**)&normedh, g_normedh);
    cudaGetSymbolAddress((void**)&wqkvt, g_wqkvt);
    cudaGetSymbolAddress((void**)&wot, g_wot);
    cudaGetSymbolAddress((void**)&wg1t, g_wg1t);
    cudaGetSymbolAddress((void**)&wg2t, g_wg2t);

    cudaFuncSetAttribute(hgemm, cudaFuncAttributeMaxDynamicSharedMemorySize, HG_SMEM);

    // 1: convert x
    k_f2h<<<MTOK * DDIM / (256 * 4), 256>>>(x, xh, MTOK * DDIM);
    // 2: all weight transposes fused
    k_tr_all<<<4224, dim3(32, 8)>>>(Wq, Wk, Wv, Wo, Wg1, Wg2, wqkvt, wot, wg1t, wg2t);
    // 3: lam/gamma projections
    k_fgamma<<<MTOK / 16, 256>>>(x, Wf, Wgamma, lam, gam);
    // 4: fused QKV GEMM (profiled slot)
    hgemm<<<dim3(24, 32), 256, HG_SMEM>>>(xh, wqkvt, qkv, QSTR, DDIM, 1, 0);
    // 5: l2norm + a
    k_norm_a<<<MTOK, 512>>>(qkv, lam, gam, a);
    // 6: delta-rule scan
    k_scan<<<64, 128>>>(qkv, a, lam, attn);
    // 7: g1 = x @ Wg1 (half out)
    hgemm<<<dim3(1, 32), 256, HG_SMEM>>>(xh, wg1t, g1h, 64, DDIM, 0, 1);
    // 8: gate = sigmoid(g1 @ Wg2)
    hgemm<<<dim3(8, 32), 256, HG_SMEM>>>(g1h, wg2t, gate, DDIM, 64, 2, 0);
    // 9: gated LayerNorm -> half
    k_ln<<<MTOK, 256>>>(attn, gate, nw, normedh);
    // 10: out = normed @ Wo
    hgemm<<<dim3(8, 32), 256, HG_SMEM>>>(normedh, wot, out, DDIM, DDIM, 0, 0);
}

// round 6
// speedup vs baseline: 3.2028x; 1.4556x over previous
#include <cuda_runtime.h>
#include <cuda_fp16.h>
#include <math.h>
#include <stdint.h>

#define MTOK 4096   // B*N
#define DDIM 1024
#define NHEAD 16
#define SEQ 2048
#define QSTR 3072   // fused qkv row stride

// ---------------- scratch (device globals; no allocs allowed) ----------------
static __device__ float g_qkv[MTOK * QSTR];      // [q | k | v] fused
static __device__ float g_a[MTOK * DDIM];
static __device__ float g_attn[MTOK * DDIM];
static __device__ float g_gate[MTOK * DDIM];
static __device__ float g_lam[MTOK * NHEAD];
static __device__ float g_gam[MTOK * NHEAD];
static __device__ __half g_xh[MTOK * DDIM];
static __device__ __half g_g1h[MTOK * 64];
static __device__ __half g_normedh[MTOK * DDIM];
static __device__ __half g_wqkvt[3 * DDIM * DDIM];
static __device__ __half g_wot[DDIM * DDIM];
static __device__ __half g_wg1t[64 * DDIM];
static __device__ __half g_wg2t[DDIM * 64];

__device__ __forceinline__ uint32_t smem_u32(const void* p) {
    uint32_t a;
    asm("{ .reg .u64 t; cvta.to.shared.u64 t, %1; cvt.u32.u64 %0, t; }" : "=r"(a) : "l"(p));
    return a;
}
__device__ __forceinline__ void cp16(uint32_t dst, const void* src, int valid) {
    int sz = valid ? 16 : 0;
    asm volatile("cp.async.cg.shared.global [%0], [%1], 16, %2;" :: "r"(dst), "l"(src), "r"(sz));
}
__device__ __forceinline__ void cp4(uint32_t dst, const void* src) {
    asm volatile("cp.async.ca.shared.global [%0], [%1], 4;" :: "r"(dst), "l"(src));
}

// ================= fp16 tensor-core GEMM: C = act(A @ Bt^T) =================
// Tile 128x128, K-tile 32, 3-stage cp.async, 2 CTAs/SM (regs capped 128).
#define ROWB 80
#define STAGEB (128 * ROWB * 2)          // 20480
#define HG_SMEM (3 * STAGEB)             // 61440

__global__ __launch_bounds__(256, 2)
void hgemm(const __half* __restrict__ A, const __half* __restrict__ Bt,
           void* __restrict__ Cout, int Ntot, int K, int act, int outHalf)
{
    extern __shared__ __align__(128) char smem[];
    const uint32_t sb = smem_u32(smem);
    const int tid = threadIdx.x, lane = tid & 31, warp = tid >> 5;
    const int wm = warp >> 2, wn = warp & 3;
    const int g = lane >> 2, tig = lane & 3;
    const int m0 = blockIdx.y * 128, n0 = blockIdx.x * 128;
    const int NC = K >> 5;

    float acc[4][4][4];
#pragma unroll
    for (int mt = 0; mt < 4; ++mt)
#pragma unroll
        for (int nt = 0; nt < 4; ++nt)
#pragma unroll
            for (int j = 0; j < 4; ++j) acc[mt][nt][j] = 0.f;

#define LOAD_TILE(kt, ss) do { \
    uint32_t aB = sb + (ss) * STAGEB; \
    uint32_t bB = aB + 128 * ROWB; \
    _Pragma("unroll") \
    for (int i = 0; i < 2; ++i) { \
        int id = tid + i * 256; \
        int r = id >> 2, c = id & 3; \
        cp16(aB + r * ROWB + c * 16, A + (size_t)(m0 + r) * K + (kt) * 32 + c * 8, 1); \
        int nr = n0 + r; int ok = nr < Ntot; int nrc = ok ? nr : 0; \
        cp16(bB + r * ROWB + c * 16, Bt + (size_t)nrc * K + (kt) * 32 + c * 8, ok); \
    } \
} while (0)

#pragma unroll
    for (int p = 0; p < 2; ++p) {
        if (p < NC) LOAD_TILE(p, p);
        asm volatile("cp.async.commit_group;" ::: "memory");
    }

    for (int kt = 0; kt < NC; ++kt) {
        asm volatile("cp.async.wait_group 1;" ::: "memory");
        __syncthreads();
        int ln = kt + 2;
        if (ln < NC) {
            int sl = ln - (ln / 3) * 3;
            LOAD_TILE(ln, sl);
        }
        asm volatile("cp.async.commit_group;" ::: "memory");

        int st = kt - (kt / 3) * 3;
        uint32_t aB = sb + st * STAGEB;
        uint32_t bB = aB + 128 * ROWB;
#pragma unroll
        for (int s = 0; s < 2; ++s) {
            uint32_t af[4][4], bf[4][2];
#pragma unroll
            for (int mt = 0; mt < 4; ++mt) {
                uint32_t addr = aB + (wm * 64 + mt * 16 + (lane & 15)) * ROWB
                              + (2 * s + (lane >> 4)) * 16;
                asm volatile("ldmatrix.sync.aligned.m8n8.x4.shared.b16 {%0,%1,%2,%3}, [%4];"
                    : "=r"(af[mt][0]), "=r"(af[mt][1]), "=r"(af[mt][2]), "=r"(af[mt][3])
                    : "r"(addr));
            }
#pragma unroll
            for (int nt = 0; nt < 4; ++nt) {
                uint32_t addr = bB + (wn * 32 + nt * 8 + (lane & 7)) * ROWB
                              + (2 * s + ((lane >> 3) & 1)) * 16;
                asm volatile("ldmatrix.sync.aligned.m8n8.x2.shared.b16 {%0,%1}, [%2];"
                    : "=r"(bf[nt][0]), "=r"(bf[nt][1]) : "r"(addr));
            }
#pragma unroll
            for (int mt = 0; mt < 4; ++mt)
#pragma unroll
                for (int nt = 0; nt < 4; ++nt) {
                    asm volatile(
                        "mma.sync.aligned.m16n8k16.row.col.f32.f16.f16.f32 "
                        "{%0,%1,%2,%3}, {%4,%5,%6,%7}, {%8,%9}, {%0,%1,%2,%3};"
                        : "+f"(acc[mt][nt][0]), "+f"(acc[mt][nt][1]),
                          "+f"(acc[mt][nt][2]), "+f"(acc[mt][nt][3])
                        : "r"(af[mt][0]), "r"(af[mt][1]), "r"(af[mt][2]), "r"(af[mt][3]),
                          "r"(bf[nt][0]), "r"(bf[nt][1]));
                }
        }
        __syncthreads();
    }
#undef LOAD_TILE

    float* Cf = (float*)Cout;
    __half* Ch = (__half*)Cout;
#pragma unroll
    for (int mt = 0; mt < 4; ++mt) {
        int row = m0 + wm * 64 + mt * 16 + g;
#pragma unroll
        for (int nt = 0; nt < 4; ++nt) {
            int col = n0 + wn * 32 + nt * 8 + tig * 2;
            if (col < Ntot) {
                float c0 = acc[mt][nt][0], c1 = acc[mt][nt][1];
                float c2 = acc[mt][nt][2], c3 = acc[mt][nt][3];
                if (act == 1) {
                    c0 = c0 / (1.f + expf(-c0)); c1 = c1 / (1.f + expf(-c1));
                    c2 = c2 / (1.f + expf(-c2)); c3 = c3 / (1.f + expf(-c3));
                } else if (act == 2) {
                    c0 = 1.f / (1.f + expf(-c0)); c1 = 1.f / (1.f + expf(-c1));
                    c2 = 1.f / (1.f + expf(-c2)); c3 = 1.f / (1.f + expf(-c3));
                }
                if (outHalf) {
                    *(__half2*)&Ch[(size_t)row * Ntot + col]       = __floats2half2_rn(c0, c1);
                    *(__half2*)&Ch[(size_t)(row + 8) * Ntot + col] = __floats2half2_rn(c2, c3);
                } else {
                    *(float2*)&Cf[(size_t)row * Ntot + col]       = make_float2(c0, c1);
                    *(float2*)&Cf[(size_t)(row + 8) * Ntot + col] = make_float2(c2, c3);
                }
            }
        }
    }
}

// ================= float -> half =================
__global__ void k_f2h(const float* __restrict__ S, __half* __restrict__ D, int n)
{
    int i = (blockIdx.x * 256 + threadIdx.x) * 4;
    if (i < n) {
        float4 f = *(const float4*)&S[i];
        *(__half2*)&D[i]     = __floats2half2_rn(f.x, f.y);
        *(__half2*)&D[i + 2] = __floats2half2_rn(f.z, f.w);
    }
}

// ================= all weight transposes+convert in ONE launch =================
__global__ void k_tr_all(const float* __restrict__ Wq, const float* __restrict__ Wk,
                         const float* __restrict__ Wv, const float* __restrict__ Wo,
                         const float* __restrict__ Wg1, const float* __restrict__ Wg2,
                         __half* __restrict__ wqkvt, __half* __restrict__ wot,
                         __half* __restrict__ wg1t, __half* __restrict__ wg2t)
{
    __shared__ float t[32][33];
    int blk = blockIdx.x;
    const float* S; __half* D; int R, C, tile;
    if (blk < 3072) {
        int seg = blk >> 10; tile = blk & 1023;
        S = (seg == 0) ? Wq : (seg == 1) ? Wk : Wv;
        D = wqkvt + (size_t)seg * DDIM * DDIM; R = DDIM; C = DDIM;
    } else if (blk < 4096) { tile = blk - 3072; S = Wo;  D = wot;  R = DDIM; C = DDIM; }
    else if (blk < 4160)   { tile = blk - 4096; S = Wg1; D = wg1t; R = DDIM; C = 64; }
    else                   { tile = blk - 4160; S = Wg2; D = wg2t; R = 64;   C = DDIM; }
    int tiles_x = C >> 5;
    int c0 = (tile % tiles_x) * 32, r0 = (tile / tiles_x) * 32;
    int x = threadIdx.x, y = threadIdx.y;   // 32 x 8
#pragma unroll
    for (int i = 0; i < 32; i += 8) t[y + i][x] = S[(size_t)(r0 + y + i) * C + c0 + x];
    __syncthreads();
#pragma unroll
    for (int i = 0; i < 32; i += 8)
        D[(size_t)(c0 + y + i) * R + r0 + x] = __float2half_rn(t[x][y + i]);
}

// ================= per-token f / gamma projections (fp32) =================
__global__ void k_fgamma(const float* __restrict__ x, const float* __restrict__ Wf,
                         const float* __restrict__ Wg, float* __restrict__ lam,
                         float* __restrict__ gam)
{
    __shared__ float xs[16][33];
    __shared__ float Ws[32][32];
    int t0 = blockIdx.x * 16;
    int tid = threadIdx.x;      // 256
    int c = tid & 31, tg = tid >> 5;
    float acc[2] = {0.f, 0.f};

    for (int k0 = 0; k0 < DDIM; k0 += 32) {
        __syncthreads();
#pragma unroll
        for (int i = 0; i < 2; ++i) {
            int idx = tid + i * 256;
            int tt = idx >> 5, kk = idx & 31;
            xs[tt][kk] = x[(size_t)(t0 + tt) * DDIM + k0 + kk];
        }
#pragma unroll
        for (int i = 0; i < 4; ++i) {
            int idx = tid + i * 256;
            int kr = idx >> 5, col = idx & 31;
            Ws[kr][col] = (col < 16) ? Wf[(k0 + kr) * NHEAD + col]
                                     : Wg[(k0 + kr) * NHEAD + (col - 16)];
        }
        __syncthreads();
#pragma unroll 8
        for (int kk = 0; kk < 32; ++kk) {
            float w = Ws[kk][c];
            acc[0] = fmaf(xs[tg * 2][kk], w, acc[0]);
            acc[1] = fmaf(xs[tg * 2 + 1][kk], w, acc[1]);
        }
    }
#pragma unroll
    for (int i = 0; i < 2; ++i) {
        int t = t0 + tg * 2 + i;
        float sg = 1.f / (1.f + expf(-acc[i]));
        if (c < 16) lam[t * NHEAD + c] = sg;
        else        gam[t * NHEAD + (c - 16)] = -sg;
    }
}

// ================= l2norm(k in qkv) per head; a = k_norm * gamma * lambda =================
__global__ void k_norm_a(float* __restrict__ qkv, const float* __restrict__ lam,
                         const float* __restrict__ gam, float* __restrict__ a)
{
    int t = blockIdx.x;
    int w = threadIdx.x >> 5;
    int lane = threadIdx.x & 31;
    size_t kb = (size_t)t * QSTR + DDIM + w * 64;
    float k0 = qkv[kb + lane], k1 = qkv[kb + lane + 32];
    float ss = k0 * k0 + k1 * k1;
#pragma unroll
    for (int o = 16; o; o >>= 1) ss += __shfl_xor_sync(0xffffffffu, ss, o);
    float inv = 1.f / fmaxf(sqrtf(ss), 1e-12f);
    float c = gam[t * NHEAD + w] * lam[t * NHEAD + w];
    float kn0 = k0 * inv, kn1 = k1 * inv;
    qkv[kb + lane] = kn0;               qkv[kb + lane + 32] = kn1;
    size_t ab = (size_t)t * DDIM + w * 64;
    a[ab + lane] = kn0 * c;             a[ab + lane + 32] = kn1 * c;
}

// ================= delta-rule scan =================
// 128 blocks = 32 (b,h) x 4 column-quarters; 128 threads = 16 cols x 8 subs.
// Double-buffered cp.async tile loads (16 tokens/tile).
// d = a.s ; u = lam*d + v ; s' = lam*s + k*u ; o = q.s'
__global__ __launch_bounds__(128)
void k_scan(const float* __restrict__ qkv, const float* __restrict__ a,
            const float* __restrict__ lamArr, float* __restrict__ o)
{
    __shared__ __align__(16) float qs[2][16][64];
    __shared__ __align__(16) float ks[2][16][64];
    __shared__ __align__(16) float as_[2][16][64];
    __shared__ __align__(16) float vs[2][16][16];
    __shared__ float lm[2][16];

    const int blk = blockIdx.x;           // 0..127
    const int bh = blk >> 2, quarter = blk & 3;
    const int b = bh >> 4, h = bh & 15;
    const int tid = threadIdx.x;          // 0..127
    const int col = tid >> 3;             // 0..15
    const int sub = tid & 7;              // 0..7
    const int tok0 = b * SEQ;
    const int hoff = h * 64;

    const uint32_t qsB = smem_u32(&qs[0][0][0]);
    const uint32_t ksB = smem_u32(&ks[0][0][0]);
    const uint32_t asB = smem_u32(&as_[0][0][0]);
    const uint32_t vsB = smem_u32(&vs[0][0][0]);
    const uint32_t lmB = smem_u32(&lm[0][0]);

#define SC_LOAD(stg, buf) do { \
    int tb_ = tok0 + (stg) * 16; \
    _Pragma("unroll") \
    for (int i = 0; i < 2; ++i) { \
        int idx = tid + i * 128; \
        int tt = idx >> 4, c4 = idx & 15; \
        uint32_t so = (uint32_t)(((buf) * 16 + tt) * 64 + c4 * 4) * 4; \
        const float* qrow = qkv + (size_t)(tb_ + tt) * QSTR + hoff + c4 * 4; \
        cp16(qsB + so, qrow, 1); \
        cp16(ksB + so, qrow + DDIM, 1); \
        cp16(asB + so, a + (size_t)(tb_ + tt) * DDIM + hoff + c4 * 4, 1); \
    } \
    if (tid < 64) { \
        int tt = tid >> 2, c4 = tid & 3; \
        uint32_t so = (uint32_t)(((buf) * 16 + tt) * 16 + c4 * 4) * 4; \
        cp16(vsB + so, qkv + (size_t)(tb_ + tt) * QSTR + 2 * DDIM + hoff + quarter * 16 + c4 * 4, 1); \
    } \
    if (tid < 16) \
        cp4(lmB + (uint32_t)((buf) * 16 + tid) * 4, lamArr + (size_t)(tb_ + tid) * NHEAD + h); \
} while (0)

    float s[8];
#pragma unroll
    for (int j = 0; j < 8; ++j) s[j] = 0.f;

    SC_LOAD(0, 0);
    asm volatile("cp.async.commit_group;" ::: "memory");
    asm volatile("cp.async.wait_group 0;" ::: "memory");
    __syncthreads();

    for (int st = 0; st < SEQ / 16; ++st) {
        const int buf = st & 1;
        if (st + 1 < SEQ / 16) {
            SC_LOAD(st + 1, buf ^ 1);
        }
        asm volatile("cp.async.commit_group;" ::: "memory");

        const int tb = tok0 + st * 16;
#pragma unroll 4
        for (int tt = 0; tt < 16; ++tt) {
            float l = lm[buf][tt];
            float4 a0 = *(const float4*)&as_[buf][tt][sub * 8];
            float4 a1 = *(const float4*)&as_[buf][tt][sub * 8 + 4];
            float d0 = a0.x * s[0] + a0.y * s[1] + a0.z * s[2] + a0.w * s[3];
            float d1 = a1.x * s[4] + a1.y * s[5] + a1.z * s[6] + a1.w * s[7];
            float dp = d0 + d1;
            dp += __shfl_xor_sync(0xffffffffu, dp, 1);
            dp += __shfl_xor_sync(0xffffffffu, dp, 2);
            dp += __shfl_xor_sync(0xffffffffu, dp, 4);
            float u = fmaf(l, dp, vs[buf][tt][col]);
            float4 k0 = *(const float4*)&ks[buf][tt][sub * 8];
            float4 k1 = *(const float4*)&ks[buf][tt][sub * 8 + 4];
            s[0] = fmaf(k0.x, u, l * s[0]); s[1] = fmaf(k0.y, u, l * s[1]);
            s[2] = fmaf(k0.z, u, l * s[2]); s[3] = fmaf(k0.w, u, l * s[3]);
            s[4] = fmaf(k1.x, u, l * s[4]); s[5] = fmaf(k1.y, u, l * s[5]);
            s[6] = fmaf(k1.z, u, l * s[6]); s[7] = fmaf(k1.w, u, l * s[7]);
            float4 q0 = *(const float4*)&qs[buf][tt][sub * 8];
            float4 q1 = *(const float4*)&qs[buf][tt][sub * 8 + 4];
            float o0 = q0.x * s[0] + q0.y * s[1] + q0.z * s[2] + q0.w * s[3];
            float o1 = q1.x * s[4] + q1.y * s[5] + q1.z * s[6] + q1.w * s[7];
            float op = o0 + o1;
            op += __shfl_xor_sync(0xffffffffu, op, 1);
            op += __shfl_xor_sync(0xffffffffu, op, 2);
            op += __shfl_xor_sync(0xffffffffu, op, 4);
            if (sub == 0)
                o[(size_t)(tb + tt) * DDIM + hoff + quarter * 16 + col] = op;
        }
        asm volatile("cp.async.wait_group 0;" ::: "memory");
        __syncthreads();
    }
#undef SC_LOAD
}

// ================= gate-multiply + LayerNorm -> half =================
__global__ void k_ln(const float* __restrict__ attn, const float* __restrict__ gate,
                     const float* __restrict__ nw, __half* __restrict__ outh)
{
    __shared__ float red[32];
    int t = blockIdx.x;
    int tid = threadIdx.x;  // 256
    int lane = tid & 31, w = tid >> 5;
    float y[4];
    float sm = 0.f;
#pragma unroll
    for (int i = 0; i < 4; ++i) {
        int j = tid + i * 256;
        y[i] = attn[(size_t)t * DDIM + j] * gate[(size_t)t * DDIM + j];
        sm += y[i];
    }
#pragma unroll
    for (int o = 16; o; o >>= 1) sm += __shfl_xor_sync(0xffffffffu, sm, o);
    if (lane == 0) red[w] = sm;
    __syncthreads();
    if (w == 0) {
        float v2 = (lane < 8) ? red[lane] : 0.f;
#pragma unroll
        for (int o = 4; o; o >>= 1) v2 += __shfl_xor_sync(0xffffffffu, v2, o);
        if (lane == 0) red[0] = v2;
    }
    __syncthreads();
    float mu = red[0] * (1.f / DDIM);
    __syncthreads();
    float vsum = 0.f;
#pragma unroll
    for (int i = 0; i < 4; ++i) { float d = y[i] - mu; vsum += d * d; }
#pragma unroll
    for (int o = 16; o; o >>= 1) vsum += __shfl_xor_sync(0xffffffffu, vsum, o);
    if (lane == 0) red[w] = vsum;
    __syncthreads();
    if (w == 0) {
        float v2 = (lane < 8) ? red[lane] : 0.f;
#pragma unroll
        for (int o = 4; o; o >>= 1) v2 += __shfl_xor_sync(0xffffffffu, v2, o);
        if (lane == 0) red[0] = v2;
    }
    __syncthreads();
    float inv = rsqrtf(red[0] * (1.f / DDIM) + 1e-5f);
#pragma unroll
    for (int i = 0; i < 4; ++i) {
        int j = tid + i * 256;
        outh[(size_t)t * DDIM + j] = __float2half_rn((y[i] - mu) * inv * nw[j]);
    }
}

// ================= launch =================
extern "C" void kernel_launch(void* const* d_in, const int* in_sizes, int n_in,
                              void* d_out, int out_size)
{
    const float* x      = (const float*)d_in[0];
    const float* Wq     = (const float*)d_in[1];
    const float* Wk     = (const float*)d_in[2];
    const float* Wv     = (const float*)d_in[3];
    const float* Wgamma = (const float*)d_in[4];
    const float* Wf     = (const float*)d_in[5];
    const float* Wg1    = (const float*)d_in[6];
    const float* Wg2    = (const float*)d_in[7];
    const float* Wo     = (const float*)d_in[8];
    const float* nw     = (const float*)d_in[9];
    float* out = (float*)d_out;

    float *qkv, *a, *attn, *gate, *lam, *gam;
    __half *xh, *g1h, *normedh, *wqkvt, *wot, *wg1t, *wg2t;
    cudaGetSymbolAddress((void**)&qkv, g_qkv);
    cudaGetSymbolAddress((void**)&a, g_a);
    cudaGetSymbolAddress((void**)&attn, g_attn);
    cudaGetSymbolAddress((void**)&gate, g_gate);
    cudaGetSymbolAddress((void**)&lam, g_lam);
    cudaGetSymbolAddress((void**)&gam, g_gam);
    cudaGetSymbolAddress((void**)&xh, g_xh);
    cudaGetSymbolAddress((void**)&g1h, g_g1h);
    cudaGetSymbolAddress((void**)&normedh, g_normedh);
    cudaGetSymbolAddress((void**)&wqkvt, g_wqkvt);
    cudaGetSymbolAddress((void**)&wot, g_wot);
    cudaGetSymbolAddress((void**)&wg1t, g_wg1t);
    cudaGetSymbolAddress((void**)&wg2t, g_wg2t);

    cudaFuncSetAttribute(hgemm, cudaFuncAttributeMaxDynamicSharedMemorySize, HG_SMEM);

    // 1: convert x
    k_f2h<<<MTOK * DDIM / (256 * 4), 256>>>(x, xh, MTOK * DDIM);
    // 2: all weight transposes fused
    k_tr_all<<<4224, dim3(32, 8)>>>(Wq, Wk, Wv, Wo, Wg1, Wg2, wqkvt, wot, wg1t, wg2t);
    // 3: lam/gamma projections
    k_fgamma<<<MTOK / 16, 256>>>(x, Wf, Wgamma, lam, gam);
    // 4: fused QKV GEMM (profiled slot)
    hgemm<<<dim3(24, 32), 256, HG_SMEM>>>(xh, wqkvt, qkv, QSTR, DDIM, 1, 0);
    // 5: l2norm + a
    k_norm_a<<<MTOK, 512>>>(qkv, lam, gam, a);
    // 6: delta-rule scan
    k_scan<<<128, 128>>>(qkv, a, lam, attn);
    // 7: g1 = x @ Wg1 (half out)
    hgemm<<<dim3(1, 32), 256, HG_SMEM>>>(xh, wg1t, g1h, 64, DDIM, 0, 1);
    // 8: gate = sigmoid(g1 @ Wg2)
    hgemm<<<dim3(8, 32), 256, HG_SMEM>>>(g1h, wg2t, gate, DDIM, 64, 2, 0);
    // 9: gated LayerNorm -> half
    k_ln<<<MTOK, 256>>>(attn, gate, nw, normedh);
    // 10: out = normed @ Wo
    hgemm<<<dim3(8, 32), 256, HG_SMEM>>>(normedh, wot, out, DDIM, DDIM, 0, 0);
}